// round 12
// baseline (speedup 1.0000x reference)
#include <cuda_runtime.h>
#include <cstdint>

#define BB 32
#define HH 56
#define HC 128
#define CC 256
#define PIX (HH*HH)          // 3136
#define EZ (BB*HC*PIX)       // 12845056
#define N1 (BB*PIX)          // 100352
#define OHH 112
#define OPIX (OHH*OHH)       // 12544
#define N2 (BB*OPIX)         // 401408

#define KP 264               // padded K stride (257 used)
#define KUSE 257
#define TPB 196              // 14x14 tiles per batch (F(4x4))
#define NT (BB*TPB)          // 6272 tiles

__device__ __align__(128) float g_z[EZ];            // conv1 out -> BEC output h
__device__ __align__(128) float g_U[36*KP*128];     // transformed weights [p][ic][oc]
__device__ __align__(128) float g_V[36*KP*NT];      // transformed inputs  [p][ic][T] (zero-init pads)
__device__ __align__(128) float g_M[36*128*NT];     // products [p][oc][T]
__device__ double g_sd1[128], g_qd1[128];           // BN1 atomic accumulators
__device__ double g_sd2[256], g_qd2[256];           // BN2 atomic accumulators
__device__ float g_m1[HC], g_rs1[HC];

// ---------------------------------------------------------------------------
// Kernel Z: zero all BN accumulators (start of every replay)
// ---------------------------------------------------------------------------
__global__ __launch_bounds__(512) void zero_kernel() {
  const int t = threadIdx.x;
  if (t < 128) { g_sd1[t] = 0.0; g_qd1[t] = 0.0; }
  if (t < 256) { g_sd2[t] = 0.0; g_qd2[t] = 0.0; }
}

// ---------------------------------------------------------------------------
// Kernel A: weight transform  U = G g G^T  for F(4x4,3x3)
// ---------------------------------------------------------------------------
__global__ __launch_bounds__(256) void uT_kernel(const float* __restrict__ w1) {
  int i = blockIdx.x * 256 + threadIdx.x;
  if (i >= KUSE * 128) return;
  int oc = i & 127, ic = i >> 7;
  float g[3][3];
#pragma unroll
  for (int r = 0; r < 3; ++r)
#pragma unroll
    for (int c = 0; c < 3; ++c) g[r][c] = w1[oc * 2313 + ic * 9 + r * 3 + c];
  float t[6][3];
#pragma unroll
  for (int c = 0; c < 3; ++c) {
    t[0][c] = 0.25f * g[0][c];
    t[1][c] = (-1.f/6.f) * (g[0][c] + g[1][c] + g[2][c]);
    t[2][c] = (1.f/6.f) * (-g[0][c] + g[1][c] - g[2][c]);
    t[3][c] = (1.f/24.f) * g[0][c] + (1.f/12.f) * g[1][c] + (1.f/6.f) * g[2][c];
    t[4][c] = (1.f/24.f) * g[0][c] - (1.f/12.f) * g[1][c] + (1.f/6.f) * g[2][c];
    t[5][c] = g[2][c];
  }
  float u[6][6];
#pragma unroll
  for (int r = 0; r < 6; ++r) {
    u[r][0] = 0.25f * t[r][0];
    u[r][1] = (-1.f/6.f) * (t[r][0] + t[r][1] + t[r][2]);
    u[r][2] = (1.f/6.f) * (-t[r][0] + t[r][1] - t[r][2]);
    u[r][3] = (1.f/24.f) * t[r][0] + (1.f/12.f) * t[r][1] + (1.f/6.f) * t[r][2];
    u[r][4] = (1.f/24.f) * t[r][0] - (1.f/12.f) * t[r][1] + (1.f/6.f) * t[r][2];
    u[r][5] = t[r][2];
  }
#pragma unroll
  for (int p = 0; p < 36; ++p)
    g_U[(p * KP + ic) * 128 + oc] = u[p / 6][p % 6];
}

// ---------------------------------------------------------------------------
// Kernel B: input transform  V = B^T d B  per 4x4-output tile (6x6 input).
// ---------------------------------------------------------------------------
__global__ __launch_bounds__(256) void vT_kernel(
    const float* __restrict__ x, const float* __restrict__ nu) {
  __shared__ float sp[58 * 58];
  const int ic = blockIdx.x, b = blockIdx.y, t = threadIdx.x;
  for (int i = t; i < 58 * 58; i += 256) sp[i] = 0.f;
  __syncthreads();
  if (ic < 256) {
    const float* xp = x + ((long)b * 256 + ic) * PIX;
    for (int i = t; i < PIX; i += 256) {
      int r = i / 56, c = i - r * 56;
      sp[(r + 1) * 58 + c + 1] = xp[i];
    }
  } else {
    const float nf = nu[0] * 0.5f;
    for (int i = t; i < PIX; i += 256) {
      int r = i / 56, c = i - r * 56;
      sp[(r + 1) * 58 + c + 1] = nf;
    }
  }
  __syncthreads();

  const int base = ic * NT + b * TPB;
  for (int tile = t; tile < TPB; tile += 256) {
    const int ty = tile / 14, tx = tile - ty * 14;
    float d[6][6];
#pragma unroll
    for (int r = 0; r < 6; ++r)
#pragma unroll
      for (int c = 0; c < 6; ++c) d[r][c] = sp[(4 * ty + r) * 58 + 4 * tx + c];
    float td[6][6];
#pragma unroll
    for (int c = 0; c < 6; ++c) {
      td[0][c] = 4.f * d[0][c] - 5.f * d[2][c] + d[4][c];
      td[1][c] = -4.f * d[1][c] - 4.f * d[2][c] + d[3][c] + d[4][c];
      td[2][c] = 4.f * d[1][c] - 4.f * d[2][c] - d[3][c] + d[4][c];
      td[3][c] = -2.f * d[1][c] - d[2][c] + 2.f * d[3][c] + d[4][c];
      td[4][c] = 2.f * d[1][c] - d[2][c] - 2.f * d[3][c] + d[4][c];
      td[5][c] = 4.f * d[1][c] - 5.f * d[3][c] + d[5][c];
    }
    float v[6][6];
#pragma unroll
    for (int r = 0; r < 6; ++r) {
      v[r][0] = 4.f * td[r][0] - 5.f * td[r][2] + td[r][4];
      v[r][1] = -4.f * td[r][1] - 4.f * td[r][2] + td[r][3] + td[r][4];
      v[r][2] = 4.f * td[r][1] - 4.f * td[r][2] - td[r][3] + td[r][4];
      v[r][3] = -2.f * td[r][1] - td[r][2] + 2.f * td[r][3] + td[r][4];
      v[r][4] = 2.f * td[r][1] - td[r][2] - 2.f * td[r][3] + td[r][4];
      v[r][5] = 4.f * td[r][1] - 5.f * td[r][3] + td[r][5];
    }
#pragma unroll
    for (int p = 0; p < 36; ++p)
      g_V[p * (KP * NT) + base + tile] = v[p / 6][p % 6];
  }
}

// ---------------------------------------------------------------------------
// Kernel C: 36 batched GEMMs  M_p[128 oc][NT] = U_p[128][257] * V_p[257][NT].
// 32 chunks of 8 + peeled k=256 step.
// ---------------------------------------------------------------------------
__global__ __launch_bounds__(256) void wgemm_kernel() {
  __shared__ float sU[2][8 * 128];
  __shared__ float sV[2][8 * 128];
  const int t = threadIdx.x;
  const int og = t >> 4, tg = t & 15;
  const int p = blockIdx.y;
  const int Tb = blockIdx.x * 128;
  const int kr = t >> 5, c4 = (t & 31) * 4;

  const float* Ug = g_U + p * (KP * 128);
  const float* Vg = g_V + (long)p * (KP * NT);

  {
    float4 u = *(const float4*)&Ug[kr * 128 + c4];
    float4 v = *(const float4*)&Vg[kr * NT + Tb + c4];
    *(float4*)&sU[0][kr * 128 + c4] = u;
    *(float4*)&sV[0][kr * 128 + c4] = v;
  }
  __syncthreads();

  float acc[64];
#pragma unroll
  for (int i = 0; i < 64; ++i) acc[i] = 0.f;

  float4 pu, pv;
  for (int ch = 0; ch < 32; ++ch) {
    const int cur = ch & 1, nxt = cur ^ 1;
    {
      const int kn = ch * 8 + 8 + kr;
      pu = *(const float4*)&Ug[kn * 128 + c4];
      pv = *(const float4*)&Vg[kn * NT + Tb + c4];
    }
#pragma unroll
    for (int k = 0; k < 8; ++k) {
      const float4 ua = *(const float4*)&sU[cur][k * 128 + og * 8];
      const float4 ub = *(const float4*)&sU[cur][k * 128 + og * 8 + 4];
      const float4 va = *(const float4*)&sV[cur][k * 128 + tg * 8];
      const float4 vb = *(const float4*)&sV[cur][k * 128 + tg * 8 + 4];
      const float uu[8] = {ua.x, ua.y, ua.z, ua.w, ub.x, ub.y, ub.z, ub.w};
      const float vv[8] = {va.x, va.y, va.z, va.w, vb.x, vb.y, vb.z, vb.w};
#pragma unroll
      for (int j = 0; j < 8; ++j)
#pragma unroll
        for (int i = 0; i < 8; ++i) acc[j * 8 + i] += uu[j] * vv[i];
    }
    *(float4*)&sU[nxt][kr * 128 + c4] = pu;
    *(float4*)&sV[nxt][kr * 128 + c4] = pv;
    __syncthreads();
  }
  {
    const float4 ua = *(const float4*)&sU[0][og * 8];
    const float4 ub = *(const float4*)&sU[0][og * 8 + 4];
    const float4 va = *(const float4*)&sV[0][tg * 8];
    const float4 vb = *(const float4*)&sV[0][tg * 8 + 4];
    const float uu[8] = {ua.x, ua.y, ua.z, ua.w, ub.x, ub.y, ub.z, ub.w};
    const float vv[8] = {va.x, va.y, va.z, va.w, vb.x, vb.y, vb.z, vb.w};
#pragma unroll
    for (int j = 0; j < 8; ++j)
#pragma unroll
      for (int i = 0; i < 8; ++i) acc[j * 8 + i] += uu[j] * vv[i];
  }

#pragma unroll
  for (int j = 0; j < 8; ++j) {
    float* dst = g_M + ((long)p * 128 + og * 8 + j) * NT + Tb + tg * 8;
    ((float4*)dst)[0] = make_float4(acc[j*8+0], acc[j*8+1], acc[j*8+2], acc[j*8+3]);
    ((float4*)dst)[1] = make_float4(acc[j*8+4], acc[j*8+5], acc[j*8+6], acc[j*8+7]);
  }
}

// ---------------------------------------------------------------------------
// Kernel D: output transform  Y = A^T M A  (+bias) -> g_z, FUSED BN1 stats.
// A block spans <= 3 distinct output channels (256 threads over 196-tile
// segments); accumulate per-channel (sum, sumsq) in smem doubles, then
// <=3 global double atomics per slot.
// ---------------------------------------------------------------------------
__global__ __launch_bounds__(256) void oT_kernel(const float* __restrict__ b1) {
  __shared__ double sS[3], sQ[3];
  __shared__ int sBoc0;
  const int t = threadIdx.x;
  const int i = blockIdx.x * 256 + t;
  const int tile = i % TPB;
  const int boc = i / TPB;
  const int oc = boc & 127, b = boc >> 7;
  const int Ti = b * TPB + tile;

  if (t == 0) { sBoc0 = (blockIdx.x * 256) / TPB; }
  if (t < 3) { sS[t] = 0.0; sQ[t] = 0.0; }
  __syncthreads();

  float m[6][6];
#pragma unroll
  for (int p = 0; p < 36; ++p)
    m[p / 6][p % 6] = g_M[((long)p * 128 + oc) * NT + Ti];

  float s[4][6];
#pragma unroll
  for (int c = 0; c < 6; ++c) {
    s[0][c] = m[0][c] + m[1][c] + m[2][c] + m[3][c] + m[4][c];
    s[1][c] = m[1][c] - m[2][c] + 2.f * m[3][c] - 2.f * m[4][c];
    s[2][c] = m[1][c] + m[2][c] + 4.f * m[3][c] + 4.f * m[4][c];
    s[3][c] = m[1][c] - m[2][c] + 8.f * m[3][c] - 8.f * m[4][c] + m[5][c];
  }
  const float bb = b1[oc];
  const int ty = tile / 14, tx = tile - ty * 14;
  float* dst = g_z + ((b * 128 + oc) * HH + 4 * ty) * HH + 4 * tx;
  float fs = 0.f, fq = 0.f;
#pragma unroll
  for (int r = 0; r < 4; ++r) {
    float y0 = s[r][0] + s[r][1] + s[r][2] + s[r][3] + s[r][4] + bb;
    float y1 = s[r][1] - s[r][2] + 2.f * s[r][3] - 2.f * s[r][4] + bb;
    float y2 = s[r][1] + s[r][2] + 4.f * s[r][3] + 4.f * s[r][4] + bb;
    float y3 = s[r][1] - s[r][2] + 8.f * s[r][3] - 8.f * s[r][4] + s[r][5] + bb;
    *(float4*)(dst + r * HH) = make_float4(y0, y1, y2, y3);
    fs += y0 + y1 + y2 + y3;
    fq += y0 * y0 + y1 * y1 + y2 * y2 + y3 * y3;
  }
  const int slot = boc - sBoc0;          // 0..2
  atomicAdd(&sS[slot], (double)fs);
  atomicAdd(&sQ[slot], (double)fq);
  __syncthreads();
  if (t < 3) {
    const int bocg = sBoc0 + t;
    if (bocg == (blockIdx.x * 256 + 255) / TPB || t == 0 ||
        bocg * TPB < (int)(blockIdx.x * 256 + 256)) {
      if (sS[t] != 0.0 || sQ[t] != 0.0) {
        atomicAdd(&g_sd1[bocg & 127], sS[t]);
        atomicAdd(&g_qd1[bocg & 127], sQ[t]);
      }
    }
  }
}

// tiny: finalize BN1 mean/rsqrt
__global__ __launch_bounds__(128) void reduce1_kernel() {
  const int c = threadIdx.x;
  double m   = g_sd1[c] / N1;
  double var = g_qd1[c] / N1 - m * m;
  g_m1[c]  = (float)m;
  g_rs1[c] = rsqrtf((float)var + 1e-5f);
}

// ---------------------------------------------------------------------------
// Threefry2x32, key (0,42), partitionable draw: x0=0, x1=j, out = o0^o1.
// ---------------------------------------------------------------------------
__device__ __forceinline__ unsigned tf_xor(unsigned j) {
  const unsigned ks0 = 0u, ks1 = 42u, ks2 = 0x1BD11BDAu ^ 42u;
  unsigned x0 = 0u + ks0;
  unsigned x1 = j  + ks1;
#define TFRND(r) { x0 += x1; x1 = __funnelshift_l(x1, x1, r); x1 ^= x0; }
  TFRND(13) TFRND(15) TFRND(26) TFRND(6)
  x0 += ks1; x1 += ks2 + 1u;
  TFRND(17) TFRND(29) TFRND(16) TFRND(24)
  x0 += ks2; x1 += ks0 + 2u;
  TFRND(13) TFRND(15) TFRND(26) TFRND(6)
  x0 += ks0; x1 += ks1 + 3u;
  TFRND(17) TFRND(29) TFRND(16) TFRND(24)
  x0 += ks1; x1 += ks2 + 4u;
  TFRND(13) TFRND(15) TFRND(26) TFRND(6)
  x0 += ks2; x1 += ks0 + 5u;
#undef TFRND
  return x0 ^ x1;
}

// ---------------------------------------------------------------------------
// Kernel 3: BN1 apply + sigmoid + quantize + BEC (in place on g_z)
// ---------------------------------------------------------------------------
__global__ __launch_bounds__(256) void bec_kernel(
    const float* __restrict__ nu, const float* __restrict__ g1,
    const float* __restrict__ be1) {
  const int e = blockIdx.x * 256 + threadIdx.x;
  const int c = (e / PIX) & 127;
  const float z = g_z[e];
  float tt = (z - g_m1[c]) * g_rs1[c] * g1[c] + be1[c];
  float s  = 0.5f * tanhf(0.5f * tt) + 0.5f;
  float r  = rintf(s * 256.0f);
  if (r >= 256.0f) r -= 256.0f;
  const unsigned xb = (unsigned)r;

  const float q = 1.0f - nu[0] * 0.5f;
  unsigned mask = 0u;
#pragma unroll
  for (int k = 0; k < 8; ++k) {
    unsigned bits = tf_xor((unsigned)(k * EZ + e));
    float u = __uint_as_float((bits >> 9) | 0x3f800000u) - 1.0f;
    if (u < q) mask |= (1u << k);
  }
  float outv = ((float)(xb & mask) + (255.0f - (float)mask) / 2.0f) / 255.0f;
  g_z[e] = outv;
}

// ---------------------------------------------------------------------------
// Kernel 4: ConvTranspose2d(k2,s2) 4-tap GEMM + FUSED BN2 partial stats.
// ---------------------------------------------------------------------------
__global__ __launch_bounds__(256) void dec_kernel(
    const float* __restrict__ w4, const float* __restrict__ b4,
    float* __restrict__ out) {
  __shared__ float4 ws4[16 * 64];
  __shared__ float4 hs4[16 * 16];
  const int t = threadIdx.x;
  const int bp = blockIdx.x;
  const int b = bp / 49;
  const int pixb = (bp % 49) * 64;
  const int cb = blockIdx.y * 64;
  const int pgrp = t & 7;
  const int cgrp = t >> 3;

  float acc[64];
#pragma unroll
  for (int i = 0; i < 64; ++i) acc[i] = 0.f;

  const float4* w44 = (const float4*)w4;
  const float4* gz4 = (const float4*)g_z;

  for (int hc0 = 0; hc0 < 128; hc0 += 16) {
    __syncthreads();
#pragma unroll
    for (int i = 0; i < 4; ++i) {
      int idx = t + i * 256;
      int hh = idx >> 6, cl = idx & 63;
      ws4[idx] = w44[(hc0 + hh) * 256 + cb + cl];
    }
    {
      int hh = t >> 4, p4 = t & 15;
      hs4[t] = gz4[((b * 128 + hc0 + hh) * PIX + pixb) / 4 + p4];
    }
    __syncthreads();
#pragma unroll
    for (int hh = 0; hh < 16; ++hh) {
      const float4 h0 = hs4[hh * 16 + pgrp * 2];
      const float4 h1 = hs4[hh * 16 + pgrp * 2 + 1];
      const float4 wa = ws4[hh * 64 + cgrp * 2];
      const float4 wb = ws4[hh * 64 + cgrp * 2 + 1];
      const float hv[8] = {h0.x, h0.y, h0.z, h0.w, h1.x, h1.y, h1.z, h1.w};
#pragma unroll
      for (int pp = 0; pp < 8; ++pp) {
        acc[pp * 4 + 0] += hv[pp] * wa.x;
        acc[pp * 4 + 1] += hv[pp] * wa.y;
        acc[pp * 4 + 2] += hv[pp] * wa.z;
        acc[pp * 4 + 3] += hv[pp] * wa.w;
        acc[32 + pp * 4 + 0] += hv[pp] * wb.x;
        acc[32 + pp * 4 + 1] += hv[pp] * wb.y;
        acc[32 + pp * 4 + 2] += hv[pp] * wb.z;
        acc[32 + pp * 4 + 3] += hv[pp] * wb.w;
      }
    }
  }

  float sums[2] = {0.f, 0.f}, sumq[2] = {0.f, 0.f};
#pragma unroll
  for (int cc = 0; cc < 2; ++cc) {
    const int c = cb + cgrp * 2 + cc;
    const float bb = b4[c];
#pragma unroll
    for (int pp = 0; pp < 8; ++pp) {
      const int pix = pixb + pgrp * 8 + pp;
      const int ih = pix / HH, iw = pix % HH;
      float* dst = out + ((b * 256 + c) * OHH + 2 * ih) * OHH + 2 * iw;
      float v0 = acc[cc * 32 + pp * 4 + 0] + bb;
      float v1 = acc[cc * 32 + pp * 4 + 1] + bb;
      float v2 = acc[cc * 32 + pp * 4 + 2] + bb;
      float v3 = acc[cc * 32 + pp * 4 + 3] + bb;
      *(float2*)dst = make_float2(v0, v1);
      *(float2*)(dst + OHH) = make_float2(v2, v3);
      sums[cc] += v0 + v1 + v2 + v3;
      sumq[cc] += v0 * v0 + v1 * v1 + v2 * v2 + v3 * v3;
    }
  }
#pragma unroll
  for (int off = 1; off < 8; off <<= 1) {
    sums[0] += __shfl_xor_sync(0xffffffffu, sums[0], off);
    sumq[0] += __shfl_xor_sync(0xffffffffu, sumq[0], off);
    sums[1] += __shfl_xor_sync(0xffffffffu, sums[1], off);
    sumq[1] += __shfl_xor_sync(0xffffffffu, sumq[1], off);
  }
  if (pgrp == 0) {
    const int c0 = cb + cgrp * 2;
    atomicAdd(&g_sd2[c0],     (double)sums[0]);
    atomicAdd(&g_qd2[c0],     (double)sumq[0]);
    atomicAdd(&g_sd2[c0 + 1], (double)sums[1]);
    atomicAdd(&g_qd2[c0 + 1], (double)sumq[1]);
  }
}

// ---------------------------------------------------------------------------
// Kernel 6: BN2 apply (stats inline from accumulators) + relu, in place
// ---------------------------------------------------------------------------
__global__ __launch_bounds__(256) void bn2_kernel(
    const float* __restrict__ g2, const float* __restrict__ be2,
    float* __restrict__ out) {
  const int i = blockIdx.x * 256 + threadIdx.x;
  const int c = (i / (OPIX / 4)) & 255;
  const double inv = 1.0 / (double)N2;
  const double md = g_sd2[c] * inv;
  const double var = g_qd2[c] * inv - md * md;
  const float m = (float)md;
  const float rs = rsqrtf((float)var + 1e-5f);
  float4 v = ((float4*)out)[i];
  const float gg = g2[c], bb = be2[c];
  v.x = fmaxf((v.x - m) * rs * gg + bb, 0.f);
  v.y = fmaxf((v.y - m) * rs * gg + bb, 0.f);
  v.z = fmaxf((v.z - m) * rs * gg + bb, 0.f);
  v.w = fmaxf((v.w - m) * rs * gg + bb, 0.f);
  ((float4*)out)[i] = v;
}

// ---------------------------------------------------------------------------
extern "C" void kernel_launch(void* const* d_in, const int* in_sizes, int n_in,
                              void* d_out, int out_size) {
  const float* x   = (const float*)d_in[0];
  const float* nu  = (const float*)d_in[1];
  const float* w1  = (const float*)d_in[2];
  const float* b1  = (const float*)d_in[3];
  const float* g1  = (const float*)d_in[4];
  const float* be1 = (const float*)d_in[5];
  const float* w4  = (const float*)d_in[6];
  const float* b4  = (const float*)d_in[7];
  const float* g2  = (const float*)d_in[8];
  const float* be2 = (const float*)d_in[9];
  float* out = (float*)d_out;

  zero_kernel<<<1, 512>>>();
  uT_kernel<<<(KUSE * 128 + 255) / 256, 256>>>(w1);
  vT_kernel<<<dim3(KUSE, 32), 256>>>(x, nu);
  wgemm_kernel<<<dim3(NT / 128, 36), 256>>>();
  oT_kernel<<<(BB * 128 * TPB) / 256, 256>>>(b1);
  reduce1_kernel<<<1, 128>>>();
  bec_kernel<<<EZ / 256, 256>>>(nu, g1, be1);
  dec_kernel<<<dim3(32 * 49, 4), 256>>>(w4, b4, out);
  bn2_kernel<<<out_size / 4 / 256, 256>>>(g2, be2, out);
}

// round 13
// speedup vs baseline: 1.0520x; 1.0520x over previous
#include <cuda_runtime.h>
#include <cstdint>

#define BB 32
#define HH 56
#define HC 128
#define CC 256
#define PIX (HH*HH)          // 3136
#define EZ (BB*HC*PIX)       // 12845056
#define N1 (BB*PIX)          // 100352
#define OHH 112
#define OPIX (OHH*OHH)       // 12544
#define N2 (BB*OPIX)         // 401408

#define KP 264               // padded K stride (257 used)
#define KUSE 257
#define TPB 196              // 14x14 tiles per batch (F(4x4))
#define NT (BB*TPB)          // 6272 tiles

__device__ __align__(128) float g_z[EZ];            // conv1 out -> BEC output h
__device__ __align__(128) float g_U[36*KP*128];     // transformed weights [p][ic][oc]
__device__ __align__(128) float g_V[36*KP*NT];      // transformed inputs  [p][ic][T] (zero-init pads)
__device__ __align__(128) float g_M[36*128*NT];     // products [p][oc][T]
__device__ double g_d1[128*8*2];                    // BN1 partials
__device__ double g_sd2[256], g_qd2[256];           // BN2 atomic accumulators
__device__ float g_m1[HC], g_rs1[HC];

// ---------------------------------------------------------------------------
// Kernel A: weight transform  U = G g G^T  for F(4x4,3x3)
// ---------------------------------------------------------------------------
__global__ __launch_bounds__(256) void uT_kernel(const float* __restrict__ w1) {
  int i = blockIdx.x * 256 + threadIdx.x;
  if (i >= KUSE * 128) return;
  int oc = i & 127, ic = i >> 7;
  float g[3][3];
#pragma unroll
  for (int r = 0; r < 3; ++r)
#pragma unroll
    for (int c = 0; c < 3; ++c) g[r][c] = w1[oc * 2313 + ic * 9 + r * 3 + c];
  float t[6][3];
#pragma unroll
  for (int c = 0; c < 3; ++c) {
    t[0][c] = 0.25f * g[0][c];
    t[1][c] = (-1.f/6.f) * (g[0][c] + g[1][c] + g[2][c]);
    t[2][c] = (1.f/6.f) * (-g[0][c] + g[1][c] - g[2][c]);
    t[3][c] = (1.f/24.f) * g[0][c] + (1.f/12.f) * g[1][c] + (1.f/6.f) * g[2][c];
    t[4][c] = (1.f/24.f) * g[0][c] - (1.f/12.f) * g[1][c] + (1.f/6.f) * g[2][c];
    t[5][c] = g[2][c];
  }
  float u[6][6];
#pragma unroll
  for (int r = 0; r < 6; ++r) {
    u[r][0] = 0.25f * t[r][0];
    u[r][1] = (-1.f/6.f) * (t[r][0] + t[r][1] + t[r][2]);
    u[r][2] = (1.f/6.f) * (-t[r][0] + t[r][1] - t[r][2]);
    u[r][3] = (1.f/24.f) * t[r][0] + (1.f/12.f) * t[r][1] + (1.f/6.f) * t[r][2];
    u[r][4] = (1.f/24.f) * t[r][0] - (1.f/12.f) * t[r][1] + (1.f/6.f) * t[r][2];
    u[r][5] = t[r][2];
  }
#pragma unroll
  for (int p = 0; p < 36; ++p)
    g_U[(p * KP + ic) * 128 + oc] = u[p / 6][p % 6];
}

// ---------------------------------------------------------------------------
// Kernel B: input transform  V = B^T d B  per 4x4-output tile (6x6 input).
// grid (257, 32 b); one (b, ic) plane in smem (58x58 padded halo).
// ---------------------------------------------------------------------------
__global__ __launch_bounds__(256) void vT_kernel(
    const float* __restrict__ x, const float* __restrict__ nu) {
  __shared__ float sp[58 * 58];
  const int ic = blockIdx.x, b = blockIdx.y, t = threadIdx.x;
  for (int i = t; i < 58 * 58; i += 256) sp[i] = 0.f;
  __syncthreads();
  if (ic < 256) {
    const float* xp = x + ((long)b * 256 + ic) * PIX;
    for (int i = t; i < PIX; i += 256) {
      int r = i / 56, c = i - r * 56;
      sp[(r + 1) * 58 + c + 1] = xp[i];
    }
  } else {
    const float nf = nu[0] * 0.5f;
    for (int i = t; i < PIX; i += 256) {
      int r = i / 56, c = i - r * 56;
      sp[(r + 1) * 58 + c + 1] = nf;
    }
  }
  __syncthreads();

  const int base = ic * NT + b * TPB;
  for (int tile = t; tile < TPB; tile += 256) {
    const int ty = tile / 14, tx = tile - ty * 14;
    float d[6][6];
#pragma unroll
    for (int r = 0; r < 6; ++r)
#pragma unroll
      for (int c = 0; c < 6; ++c) d[r][c] = sp[(4 * ty + r) * 58 + 4 * tx + c];
    float td[6][6];
#pragma unroll
    for (int c = 0; c < 6; ++c) {
      td[0][c] = 4.f * d[0][c] - 5.f * d[2][c] + d[4][c];
      td[1][c] = -4.f * d[1][c] - 4.f * d[2][c] + d[3][c] + d[4][c];
      td[2][c] = 4.f * d[1][c] - 4.f * d[2][c] - d[3][c] + d[4][c];
      td[3][c] = -2.f * d[1][c] - d[2][c] + 2.f * d[3][c] + d[4][c];
      td[4][c] = 2.f * d[1][c] - d[2][c] - 2.f * d[3][c] + d[4][c];
      td[5][c] = 4.f * d[1][c] - 5.f * d[3][c] + d[5][c];
    }
    float v[6][6];
#pragma unroll
    for (int r = 0; r < 6; ++r) {
      v[r][0] = 4.f * td[r][0] - 5.f * td[r][2] + td[r][4];
      v[r][1] = -4.f * td[r][1] - 4.f * td[r][2] + td[r][3] + td[r][4];
      v[r][2] = 4.f * td[r][1] - 4.f * td[r][2] - td[r][3] + td[r][4];
      v[r][3] = -2.f * td[r][1] - td[r][2] + 2.f * td[r][3] + td[r][4];
      v[r][4] = 2.f * td[r][1] - td[r][2] - 2.f * td[r][3] + td[r][4];
      v[r][5] = 4.f * td[r][1] - 5.f * td[r][3] + td[r][5];
    }
#pragma unroll
    for (int p = 0; p < 36; ++p)
      g_V[p * (KP * NT) + base + tile] = v[p / 6][p % 6];
  }
}

// ---------------------------------------------------------------------------
// Kernel C: 36 batched GEMMs  M_p[128 oc][NT] = U_p[128][K=257] * V_p[257][NT].
// 32 full chunks of 8 (k 0..255) + single peeled step k=256.
// ---------------------------------------------------------------------------
__global__ __launch_bounds__(256) void wgemm_kernel() {
  __shared__ float sU[2][8 * 128];
  __shared__ float sV[2][8 * 128];
  const int t = threadIdx.x;
  const int og = t >> 4, tg = t & 15;
  const int p = blockIdx.y;
  const int Tb = blockIdx.x * 128;
  const int kr = t >> 5, c4 = (t & 31) * 4;

  const float* Ug = g_U + p * (KP * 128);
  const float* Vg = g_V + (long)p * (KP * NT);

  {
    float4 u = *(const float4*)&Ug[kr * 128 + c4];
    float4 v = *(const float4*)&Vg[kr * NT + Tb + c4];
    *(float4*)&sU[0][kr * 128 + c4] = u;
    *(float4*)&sV[0][kr * 128 + c4] = v;
  }
  __syncthreads();

  float acc[64];
#pragma unroll
  for (int i = 0; i < 64; ++i) acc[i] = 0.f;

  float4 pu, pv;
  for (int ch = 0; ch < 32; ++ch) {
    const int cur = ch & 1, nxt = cur ^ 1;
    {
      const int kn = ch * 8 + 8 + kr;   // rows 8..263 (257+ zero-init, unused)
      pu = *(const float4*)&Ug[kn * 128 + c4];
      pv = *(const float4*)&Vg[kn * NT + Tb + c4];
    }
#pragma unroll
    for (int k = 0; k < 8; ++k) {
      const float4 ua = *(const float4*)&sU[cur][k * 128 + og * 8];
      const float4 ub = *(const float4*)&sU[cur][k * 128 + og * 8 + 4];
      const float4 va = *(const float4*)&sV[cur][k * 128 + tg * 8];
      const float4 vb = *(const float4*)&sV[cur][k * 128 + tg * 8 + 4];
      const float uu[8] = {ua.x, ua.y, ua.z, ua.w, ub.x, ub.y, ub.z, ub.w};
      const float vv[8] = {va.x, va.y, va.z, va.w, vb.x, vb.y, vb.z, vb.w};
#pragma unroll
      for (int j = 0; j < 8; ++j)
#pragma unroll
        for (int i = 0; i < 8; ++i) acc[j * 8 + i] += uu[j] * vv[i];
    }
    *(float4*)&sU[nxt][kr * 128 + c4] = pu;
    *(float4*)&sV[nxt][kr * 128 + c4] = pv;
    __syncthreads();
  }
  // peeled final step: k = 256 (buffer 0 holds rows 256..263)
  {
    const float4 ua = *(const float4*)&sU[0][og * 8];
    const float4 ub = *(const float4*)&sU[0][og * 8 + 4];
    const float4 va = *(const float4*)&sV[0][tg * 8];
    const float4 vb = *(const float4*)&sV[0][tg * 8 + 4];
    const float uu[8] = {ua.x, ua.y, ua.z, ua.w, ub.x, ub.y, ub.z, ub.w};
    const float vv[8] = {va.x, va.y, va.z, va.w, vb.x, vb.y, vb.z, vb.w};
#pragma unroll
    for (int j = 0; j < 8; ++j)
#pragma unroll
      for (int i = 0; i < 8; ++i) acc[j * 8 + i] += uu[j] * vv[i];
  }

#pragma unroll
  for (int j = 0; j < 8; ++j) {
    float* dst = g_M + ((long)p * 128 + og * 8 + j) * NT + Tb + tg * 8;
    ((float4*)dst)[0] = make_float4(acc[j*8+0], acc[j*8+1], acc[j*8+2], acc[j*8+3]);
    ((float4*)dst)[1] = make_float4(acc[j*8+4], acc[j*8+5], acc[j*8+6], acc[j*8+7]);
  }
}

// ---------------------------------------------------------------------------
// Kernel D: output transform  Y = A^T M A  (+bias) -> g_z   (4x4 outputs)
// ---------------------------------------------------------------------------
__global__ __launch_bounds__(256) void oT_kernel(const float* __restrict__ b1) {
  const int i = blockIdx.x * 256 + threadIdx.x;
  const int tile = i % TPB;
  const int boc = i / TPB;
  const int oc = boc & 127, b = boc >> 7;
  const int Ti = b * TPB + tile;

  float m[6][6];
#pragma unroll
  for (int p = 0; p < 36; ++p)
    m[p / 6][p % 6] = g_M[((long)p * 128 + oc) * NT + Ti];

  float s[4][6];
#pragma unroll
  for (int c = 0; c < 6; ++c) {
    s[0][c] = m[0][c] + m[1][c] + m[2][c] + m[3][c] + m[4][c];
    s[1][c] = m[1][c] - m[2][c] + 2.f * m[3][c] - 2.f * m[4][c];
    s[2][c] = m[1][c] + m[2][c] + 4.f * m[3][c] + 4.f * m[4][c];
    s[3][c] = m[1][c] - m[2][c] + 8.f * m[3][c] - 8.f * m[4][c] + m[5][c];
  }
  const float bb = b1[oc];
  const int ty = tile / 14, tx = tile - ty * 14;
  float* dst = g_z + ((b * 128 + oc) * HH + 4 * ty) * HH + 4 * tx;
#pragma unroll
  for (int r = 0; r < 4; ++r) {
    float y0 = s[r][0] + s[r][1] + s[r][2] + s[r][3] + s[r][4] + bb;
    float y1 = s[r][1] - s[r][2] + 2.f * s[r][3] - 2.f * s[r][4] + bb;
    float y2 = s[r][1] + s[r][2] + 4.f * s[r][3] + 4.f * s[r][4] + bb;
    float y3 = s[r][1] - s[r][2] + 8.f * s[r][3] - 8.f * s[r][4] + s[r][5] + bb;
    *(float4*)(dst + r * HH) = make_float4(y0, y1, y2, y3);
  }
}

// ---------------------------------------------------------------------------
// Kernel 2a: BN1 partial stats — grid (128 ch, 8 slices)
// ---------------------------------------------------------------------------
__global__ __launch_bounds__(256) void stats1a_kernel() {
  const int c = blockIdx.x, sl = blockIdx.y, t = threadIdx.x;
  double s = 0.0, q = 0.0;
  for (int bb = sl * 4; bb < sl * 4 + 4; ++bb) {
    const float4* p = (const float4*)(g_z + (bb * 128 + c) * PIX);
    for (int i = t; i < PIX / 4; i += 256) {
      float4 v = p[i];
      s += (double)v.x + v.y + v.z + v.w;
      q += (double)v.x * v.x + (double)v.y * v.y +
           (double)v.z * v.z + (double)v.w * v.w;
    }
  }
  __shared__ double ss[256], sq[256];
  ss[t] = s; sq[t] = q;
  __syncthreads();
  for (int o = 128; o > 0; o >>= 1) {
    if (t < o) { ss[t] += ss[t + o]; sq[t] += sq[t + o]; }
    __syncthreads();
  }
  if (t == 0) {
    g_d1[(c * 8 + sl) * 2 + 0] = ss[0];
    g_d1[(c * 8 + sl) * 2 + 1] = sq[0];
  }
}

__global__ __launch_bounds__(128) void reduce1_kernel() {
  const int c = threadIdx.x;
  double s = 0.0, q = 0.0;
#pragma unroll
  for (int sl = 0; sl < 8; ++sl) {
    s += g_d1[(c * 8 + sl) * 2 + 0];
    q += g_d1[(c * 8 + sl) * 2 + 1];
  }
  double m   = s / N1;
  double var = q / N1 - m * m;
  g_m1[c]  = (float)m;
  g_rs1[c] = rsqrtf((float)var + 1e-5f);
}

// zero BN2 accumulators (before dec each replay)
__global__ __launch_bounds__(512) void zero2_kernel() {
  const int t = threadIdx.x;
  if (t < 256) { g_sd2[t] = 0.0; g_qd2[t] = 0.0; }
}

// ---------------------------------------------------------------------------
// Threefry2x32, key (0,42), partitionable draw: x0=0, x1=j, out = o0^o1.
// ---------------------------------------------------------------------------
__device__ __forceinline__ unsigned tf_xor(unsigned j) {
  const unsigned ks0 = 0u, ks1 = 42u, ks2 = 0x1BD11BDAu ^ 42u;
  unsigned x0 = 0u + ks0;
  unsigned x1 = j  + ks1;
#define TFRND(r) { x0 += x1; x1 = __funnelshift_l(x1, x1, r); x1 ^= x0; }
  TFRND(13) TFRND(15) TFRND(26) TFRND(6)
  x0 += ks1; x1 += ks2 + 1u;
  TFRND(17) TFRND(29) TFRND(16) TFRND(24)
  x0 += ks2; x1 += ks0 + 2u;
  TFRND(13) TFRND(15) TFRND(26) TFRND(6)
  x0 += ks0; x1 += ks1 + 3u;
  TFRND(17) TFRND(29) TFRND(16) TFRND(24)
  x0 += ks1; x1 += ks2 + 4u;
  TFRND(13) TFRND(15) TFRND(26) TFRND(6)
  x0 += ks2; x1 += ks0 + 5u;
#undef TFRND
  return x0 ^ x1;
}

// ---------------------------------------------------------------------------
// Kernel 3: BN1 apply + sigmoid + quantize + BEC (in place on g_z)
// ---------------------------------------------------------------------------
__global__ __launch_bounds__(256) void bec_kernel(
    const float* __restrict__ nu, const float* __restrict__ g1,
    const float* __restrict__ be1) {
  const int e = blockIdx.x * 256 + threadIdx.x;
  const int c = (e / PIX) & 127;
  const float z = g_z[e];
  float tt = (z - g_m1[c]) * g_rs1[c] * g1[c] + be1[c];
  float s  = 0.5f * tanhf(0.5f * tt) + 0.5f;
  float r  = rintf(s * 256.0f);
  if (r >= 256.0f) r -= 256.0f;
  const unsigned xb = (unsigned)r;

  const float q = 1.0f - nu[0] * 0.5f;
  unsigned mask = 0u;
#pragma unroll
  for (int k = 0; k < 8; ++k) {
    unsigned bits = tf_xor((unsigned)(k * EZ + e));
    float u = __uint_as_float((bits >> 9) | 0x3f800000u) - 1.0f;
    if (u < q) mask |= (1u << k);
  }
  float outv = ((float)(xb & mask) + (255.0f - (float)mask) / 2.0f) / 255.0f;
  g_z[e] = outv;
}

// ---------------------------------------------------------------------------
// Kernel 4: ConvTranspose2d(k2,s2) 4-tap GEMM + FUSED BN2 partial stats.
// ---------------------------------------------------------------------------
__global__ __launch_bounds__(256) void dec_kernel(
    const float* __restrict__ w4, const float* __restrict__ b4,
    float* __restrict__ out) {
  __shared__ float4 ws4[16 * 64];
  __shared__ float4 hs4[16 * 16];
  const int t = threadIdx.x;
  const int bp = blockIdx.x;
  const int b = bp / 49;
  const int pixb = (bp % 49) * 64;
  const int cb = blockIdx.y * 64;
  const int pgrp = t & 7;
  const int cgrp = t >> 3;

  float acc[64];
#pragma unroll
  for (int i = 0; i < 64; ++i) acc[i] = 0.f;

  const float4* w44 = (const float4*)w4;
  const float4* gz4 = (const float4*)g_z;

  for (int hc0 = 0; hc0 < 128; hc0 += 16) {
    __syncthreads();
#pragma unroll
    for (int i = 0; i < 4; ++i) {
      int idx = t + i * 256;
      int hh = idx >> 6, cl = idx & 63;
      ws4[idx] = w44[(hc0 + hh) * 256 + cb + cl];
    }
    {
      int hh = t >> 4, p4 = t & 15;
      hs4[t] = gz4[((b * 128 + hc0 + hh) * PIX + pixb) / 4 + p4];
    }
    __syncthreads();
#pragma unroll
    for (int hh = 0; hh < 16; ++hh) {
      const float4 h0 = hs4[hh * 16 + pgrp * 2];
      const float4 h1 = hs4[hh * 16 + pgrp * 2 + 1];
      const float4 wa = ws4[hh * 64 + cgrp * 2];
      const float4 wb = ws4[hh * 64 + cgrp * 2 + 1];
      const float hv[8] = {h0.x, h0.y, h0.z, h0.w, h1.x, h1.y, h1.z, h1.w};
#pragma unroll
      for (int pp = 0; pp < 8; ++pp) {
        acc[pp * 4 + 0] += hv[pp] * wa.x;
        acc[pp * 4 + 1] += hv[pp] * wa.y;
        acc[pp * 4 + 2] += hv[pp] * wa.z;
        acc[pp * 4 + 3] += hv[pp] * wa.w;
        acc[32 + pp * 4 + 0] += hv[pp] * wb.x;
        acc[32 + pp * 4 + 1] += hv[pp] * wb.y;
        acc[32 + pp * 4 + 2] += hv[pp] * wb.z;
        acc[32 + pp * 4 + 3] += hv[pp] * wb.w;
      }
    }
  }

  float sums[2] = {0.f, 0.f}, sumq[2] = {0.f, 0.f};
#pragma unroll
  for (int cc = 0; cc < 2; ++cc) {
    const int c = cb + cgrp * 2 + cc;
    const float bb = b4[c];
#pragma unroll
    for (int pp = 0; pp < 8; ++pp) {
      const int pix = pixb + pgrp * 8 + pp;
      const int ih = pix / HH, iw = pix % HH;
      float* dst = out + ((b * 256 + c) * OHH + 2 * ih) * OHH + 2 * iw;
      float v0 = acc[cc * 32 + pp * 4 + 0] + bb;
      float v1 = acc[cc * 32 + pp * 4 + 1] + bb;
      float v2 = acc[cc * 32 + pp * 4 + 2] + bb;
      float v3 = acc[cc * 32 + pp * 4 + 3] + bb;
      *(float2*)dst = make_float2(v0, v1);
      *(float2*)(dst + OHH) = make_float2(v2, v3);
      sums[cc] += v0 + v1 + v2 + v3;
      sumq[cc] += v0 * v0 + v1 * v1 + v2 * v2 + v3 * v3;
    }
  }
  // reduce over the 8 lanes sharing (cgrp) — consecutive lanes in warp
#pragma unroll
  for (int off = 1; off < 8; off <<= 1) {
    sums[0] += __shfl_xor_sync(0xffffffffu, sums[0], off);
    sumq[0] += __shfl_xor_sync(0xffffffffu, sumq[0], off);
    sums[1] += __shfl_xor_sync(0xffffffffu, sums[1], off);
    sumq[1] += __shfl_xor_sync(0xffffffffu, sumq[1], off);
  }
  if (pgrp == 0) {
    const int c0 = cb + cgrp * 2;
    atomicAdd(&g_sd2[c0],     (double)sums[0]);
    atomicAdd(&g_qd2[c0],     (double)sumq[0]);
    atomicAdd(&g_sd2[c0 + 1], (double)sums[1]);
    atomicAdd(&g_qd2[c0 + 1], (double)sumq[1]);
  }
}

// ---------------------------------------------------------------------------
// Kernel 6: BN2 apply (stats inline from accumulators) + relu, in place
// ---------------------------------------------------------------------------
__global__ __launch_bounds__(256) void bn2_kernel(
    const float* __restrict__ g2, const float* __restrict__ be2,
    float* __restrict__ out) {
  const int i = blockIdx.x * 256 + threadIdx.x;
  const int c = (i / (OPIX / 4)) & 255;
  const double inv = 1.0 / (double)N2;
  const double md = g_sd2[c] * inv;
  const double var = g_qd2[c] * inv - md * md;
  const float m = (float)md;
  const float rs = rsqrtf((float)var + 1e-5f);
  float4 v = ((float4*)out)[i];
  const float gg = g2[c], bb = be2[c];
  v.x = fmaxf((v.x - m) * rs * gg + bb, 0.f);
  v.y = fmaxf((v.y - m) * rs * gg + bb, 0.f);
  v.z = fmaxf((v.z - m) * rs * gg + bb, 0.f);
  v.w = fmaxf((v.w - m) * rs * gg + bb, 0.f);
  ((float4*)out)[i] = v;
}

// ---------------------------------------------------------------------------
extern "C" void kernel_launch(void* const* d_in, const int* in_sizes, int n_in,
                              void* d_out, int out_size) {
  const float* x   = (const float*)d_in[0];
  const float* nu  = (const float*)d_in[1];
  const float* w1  = (const float*)d_in[2];
  const float* b1  = (const float*)d_in[3];
  const float* g1  = (const float*)d_in[4];
  const float* be1 = (const float*)d_in[5];
  const float* w4  = (const float*)d_in[6];
  const float* b4  = (const float*)d_in[7];
  const float* g2  = (const float*)d_in[8];
  const float* be2 = (const float*)d_in[9];
  float* out = (float*)d_out;

  uT_kernel<<<(KUSE * 128 + 255) / 256, 256>>>(w1);
  vT_kernel<<<dim3(KUSE, 32), 256>>>(x, nu);
  wgemm_kernel<<<dim3(NT / 128, 36), 256>>>();
  oT_kernel<<<(BB * 128 * TPB) / 256, 256>>>(b1);
  stats1a_kernel<<<dim3(128, 8), 256>>>();
  reduce1_kernel<<<1, 128>>>();
  zero2_kernel<<<1, 512>>>();
  bec_kernel<<<EZ / 256, 256>>>(nu, g1, be1);
  dec_kernel<<<dim3(32 * 49, 4), 256>>>(w4, b4, out);
  bn2_kernel<<<out_size / 4 / 256, 256>>>(g2, be2, out);
}

// round 14
// speedup vs baseline: 1.0947x; 1.0406x over previous
#include <cuda_runtime.h>
#include <cstdint>

#define BB 32
#define HH 56
#define HC 128
#define CC 256
#define PIX (HH*HH)          // 3136
#define EZ (BB*HC*PIX)       // 12845056
#define N1 (BB*PIX)          // 100352
#define OHH 112
#define OPIX (OHH*OHH)       // 12544
#define N2 (BB*OPIX)         // 401408

#define KP 272               // padded K stride (257 used; pad for chunk-16 prefetch)
#define KUSE 257
#define TPB 196              // 14x14 tiles per batch (F(4x4))
#define NT (BB*TPB)          // 6272 tiles

__device__ __align__(128) float g_z[EZ];            // conv1 out -> BEC output h
__device__ __align__(128) float g_U[36*KP*128];     // transformed weights [p][ic][oc]
__device__ __align__(128) float g_V[36*KP*NT];      // transformed inputs  [p][ic][T] (zero-init pads)
__device__ __align__(128) float g_M[36*128*NT];     // products [p][oc][T]
__device__ double g_d1[128*8*2];                    // BN1 partials
__device__ double g_sd2[256], g_qd2[256];           // BN2 atomic accumulators
__device__ float g_m1[HC], g_rs1[HC];

#define CPASYNC16(dst, src) \
  asm volatile("cp.async.ca.shared.global [%0], [%1], 16;" :: "r"(dst), "l"(src))
#define CPCOMMIT() asm volatile("cp.async.commit_group;" ::: "memory")
#define CPWAIT0()  asm volatile("cp.async.wait_group 0;" ::: "memory")

// ---------------------------------------------------------------------------
// Kernel A: weight transform  U = G g G^T  for F(4x4,3x3)
// ---------------------------------------------------------------------------
__global__ __launch_bounds__(256) void uT_kernel(const float* __restrict__ w1) {
  int i = blockIdx.x * 256 + threadIdx.x;
  if (i >= KUSE * 128) return;
  int oc = i & 127, ic = i >> 7;
  float g[3][3];
#pragma unroll
  for (int r = 0; r < 3; ++r)
#pragma unroll
    for (int c = 0; c < 3; ++c) g[r][c] = w1[oc * 2313 + ic * 9 + r * 3 + c];
  float t[6][3];
#pragma unroll
  for (int c = 0; c < 3; ++c) {
    t[0][c] = 0.25f * g[0][c];
    t[1][c] = (-1.f/6.f) * (g[0][c] + g[1][c] + g[2][c]);
    t[2][c] = (1.f/6.f) * (-g[0][c] + g[1][c] - g[2][c]);
    t[3][c] = (1.f/24.f) * g[0][c] + (1.f/12.f) * g[1][c] + (1.f/6.f) * g[2][c];
    t[4][c] = (1.f/24.f) * g[0][c] - (1.f/12.f) * g[1][c] + (1.f/6.f) * g[2][c];
    t[5][c] = g[2][c];
  }
  float u[6][6];
#pragma unroll
  for (int r = 0; r < 6; ++r) {
    u[r][0] = 0.25f * t[r][0];
    u[r][1] = (-1.f/6.f) * (t[r][0] + t[r][1] + t[r][2]);
    u[r][2] = (1.f/6.f) * (-t[r][0] + t[r][1] - t[r][2]);
    u[r][3] = (1.f/24.f) * t[r][0] + (1.f/12.f) * t[r][1] + (1.f/6.f) * t[r][2];
    u[r][4] = (1.f/24.f) * t[r][0] - (1.f/12.f) * t[r][1] + (1.f/6.f) * t[r][2];
    u[r][5] = t[r][2];
  }
#pragma unroll
  for (int p = 0; p < 36; ++p)
    g_U[(p * KP + ic) * 128 + oc] = u[p / 6][p % 6];
}

// ---------------------------------------------------------------------------
// Kernel B: input transform  V = B^T d B  per 4x4-output tile (6x6 input).
// grid (257, 32 b); one (b, ic) plane in smem (58x58 padded halo).
// ---------------------------------------------------------------------------
__global__ __launch_bounds__(256) void vT_kernel(
    const float* __restrict__ x, const float* __restrict__ nu) {
  __shared__ float sp[58 * 58];
  const int ic = blockIdx.x, b = blockIdx.y, t = threadIdx.x;
  for (int i = t; i < 58 * 58; i += 256) sp[i] = 0.f;
  __syncthreads();
  if (ic < 256) {
    const float* xp = x + ((long)b * 256 + ic) * PIX;
    for (int i = t; i < PIX; i += 256) {
      int r = i / 56, c = i - r * 56;
      sp[(r + 1) * 58 + c + 1] = xp[i];
    }
  } else {
    const float nf = nu[0] * 0.5f;
    for (int i = t; i < PIX; i += 256) {
      int r = i / 56, c = i - r * 56;
      sp[(r + 1) * 58 + c + 1] = nf;
    }
  }
  __syncthreads();

  const int base = ic * NT + b * TPB;
  for (int tile = t; tile < TPB; tile += 256) {
    const int ty = tile / 14, tx = tile - ty * 14;
    float d[6][6];
#pragma unroll
    for (int r = 0; r < 6; ++r)
#pragma unroll
      for (int c = 0; c < 6; ++c) d[r][c] = sp[(4 * ty + r) * 58 + 4 * tx + c];
    float td[6][6];
#pragma unroll
    for (int c = 0; c < 6; ++c) {
      td[0][c] = 4.f * d[0][c] - 5.f * d[2][c] + d[4][c];
      td[1][c] = -4.f * d[1][c] - 4.f * d[2][c] + d[3][c] + d[4][c];
      td[2][c] = 4.f * d[1][c] - 4.f * d[2][c] - d[3][c] + d[4][c];
      td[3][c] = -2.f * d[1][c] - d[2][c] + 2.f * d[3][c] + d[4][c];
      td[4][c] = 2.f * d[1][c] - d[2][c] - 2.f * d[3][c] + d[4][c];
      td[5][c] = 4.f * d[1][c] - 5.f * d[3][c] + d[5][c];
    }
    float v[6][6];
#pragma unroll
    for (int r = 0; r < 6; ++r) {
      v[r][0] = 4.f * td[r][0] - 5.f * td[r][2] + td[r][4];
      v[r][1] = -4.f * td[r][1] - 4.f * td[r][2] + td[r][3] + td[r][4];
      v[r][2] = 4.f * td[r][1] - 4.f * td[r][2] - td[r][3] + td[r][4];
      v[r][3] = -2.f * td[r][1] - td[r][2] + 2.f * td[r][3] + td[r][4];
      v[r][4] = 2.f * td[r][1] - td[r][2] - 2.f * td[r][3] + td[r][4];
      v[r][5] = 4.f * td[r][1] - 5.f * td[r][3] + td[r][5];
    }
#pragma unroll
    for (int p = 0; p < 36; ++p)
      g_V[p * (KP * NT) + base + tile] = v[p / 6][p % 6];
  }
}

// ---------------------------------------------------------------------------
// Kernel C: 36 batched GEMMs  M_p[128 oc][NT] = U_p[128][K=257] * V_p[257][NT].
// cp.async double-buffered K-chunks of 16 (17 syncs), peeled k=256 step.
// Accumulation order: k = 0..256 ascending (identical to prior rounds).
// ---------------------------------------------------------------------------
__global__ __launch_bounds__(256) void wgemm_kernel() {
  __shared__ float sU[2][16 * 128];
  __shared__ float sV[2][16 * 128];
  const int t = threadIdx.x;
  const int og = t >> 4, tg = t & 15;
  const int p = blockIdx.y;
  const int Tb = blockIdx.x * 128;
  const int rA = t >> 5, cA = (t & 31) * 4;   // float4 slot: rows rA and rA+8

  const float* Ug = g_U + p * (KP * 128);
  const float* Vg = g_V + (long)p * (KP * NT);

  const uint32_t sUb = (uint32_t)__cvta_generic_to_shared(&sU[0][0]);
  const uint32_t sVb = (uint32_t)__cvta_generic_to_shared(&sV[0][0]);

  // stage chunk ch (16 k-rows) into buffer buf; 4 cp.async per thread
#define STAGE(buf, ch) do {                                                   \
    const int kb_ = (ch) * 16;                                                \
    uint32_t du_ = sUb + ((buf) * 2048 + rA * 128 + cA) * 4;                  \
    CPASYNC16(du_,            Ug + (kb_ + rA) * 128 + cA);                    \
    CPASYNC16(du_ + 4096,     Ug + (kb_ + rA + 8) * 128 + cA);                \
    uint32_t dv_ = sVb + ((buf) * 2048 + rA * 128 + cA) * 4;                  \
    CPASYNC16(dv_,            Vg + (long)(kb_ + rA) * NT + Tb + cA);          \
    CPASYNC16(dv_ + 4096,     Vg + (long)(kb_ + rA + 8) * NT + Tb + cA);      \
    CPCOMMIT();                                                               \
  } while (0)

  STAGE(0, 0);
  CPWAIT0();
  __syncthreads();

  float acc[64];
#pragma unroll
  for (int i = 0; i < 64; ++i) acc[i] = 0.f;

  for (int ch = 0; ch < 16; ++ch) {
    const int cur = ch & 1, nxt = cur ^ 1;
    STAGE(nxt, ch + 1);    // chunk 16 rows 256..271 stay < KP=272 (zero pads)
#pragma unroll
    for (int k = 0; k < 16; ++k) {
      const float4 ua = *(const float4*)&sU[cur][k * 128 + og * 8];
      const float4 ub = *(const float4*)&sU[cur][k * 128 + og * 8 + 4];
      const float4 va = *(const float4*)&sV[cur][k * 128 + tg * 8];
      const float4 vb = *(const float4*)&sV[cur][k * 128 + tg * 8 + 4];
      const float uu[8] = {ua.x, ua.y, ua.z, ua.w, ub.x, ub.y, ub.z, ub.w};
      const float vv[8] = {va.x, va.y, va.z, va.w, vb.x, vb.y, vb.z, vb.w};
#pragma unroll
      for (int j = 0; j < 8; ++j)
#pragma unroll
        for (int i = 0; i < 8; ++i) acc[j * 8 + i] += uu[j] * vv[i];
    }
    CPWAIT0();
    __syncthreads();
  }
  // peeled final step: k = 256 = row 0 of chunk 16, which sits in buffer 0
  {
    const float4 ua = *(const float4*)&sU[0][og * 8];
    const float4 ub = *(const float4*)&sU[0][og * 8 + 4];
    const float4 va = *(const float4*)&sV[0][tg * 8];
    const float4 vb = *(const float4*)&sV[0][tg * 8 + 4];
    const float uu[8] = {ua.x, ua.y, ua.z, ua.w, ub.x, ub.y, ub.z, ub.w};
    const float vv[8] = {va.x, va.y, va.z, va.w, vb.x, vb.y, vb.z, vb.w};
#pragma unroll
    for (int j = 0; j < 8; ++j)
#pragma unroll
      for (int i = 0; i < 8; ++i) acc[j * 8 + i] += uu[j] * vv[i];
  }
#undef STAGE

#pragma unroll
  for (int j = 0; j < 8; ++j) {
    float* dst = g_M + ((long)p * 128 + og * 8 + j) * NT + Tb + tg * 8;
    ((float4*)dst)[0] = make_float4(acc[j*8+0], acc[j*8+1], acc[j*8+2], acc[j*8+3]);
    ((float4*)dst)[1] = make_float4(acc[j*8+4], acc[j*8+5], acc[j*8+6], acc[j*8+7]);
  }
}

// ---------------------------------------------------------------------------
// Kernel D: output transform  Y = A^T M A  (+bias) -> g_z   (4x4 outputs)
// ---------------------------------------------------------------------------
__global__ __launch_bounds__(256) void oT_kernel(const float* __restrict__ b1) {
  const int i = blockIdx.x * 256 + threadIdx.x;
  const int tile = i % TPB;
  const int boc = i / TPB;
  const int oc = boc & 127, b = boc >> 7;
  const int Ti = b * TPB + tile;

  float m[6][6];
#pragma unroll
  for (int p = 0; p < 36; ++p)
    m[p / 6][p % 6] = g_M[((long)p * 128 + oc) * NT + Ti];

  float s[4][6];
#pragma unroll
  for (int c = 0; c < 6; ++c) {
    s[0][c] = m[0][c] + m[1][c] + m[2][c] + m[3][c] + m[4][c];
    s[1][c] = m[1][c] - m[2][c] + 2.f * m[3][c] - 2.f * m[4][c];
    s[2][c] = m[1][c] + m[2][c] + 4.f * m[3][c] + 4.f * m[4][c];
    s[3][c] = m[1][c] - m[2][c] + 8.f * m[3][c] - 8.f * m[4][c] + m[5][c];
  }
  const float bb = b1[oc];
  const int ty = tile / 14, tx = tile - ty * 14;
  float* dst = g_z + ((b * 128 + oc) * HH + 4 * ty) * HH + 4 * tx;
#pragma unroll
  for (int r = 0; r < 4; ++r) {
    float y0 = s[r][0] + s[r][1] + s[r][2] + s[r][3] + s[r][4] + bb;
    float y1 = s[r][1] - s[r][2] + 2.f * s[r][3] - 2.f * s[r][4] + bb;
    float y2 = s[r][1] + s[r][2] + 4.f * s[r][3] + 4.f * s[r][4] + bb;
    float y3 = s[r][1] - s[r][2] + 8.f * s[r][3] - 8.f * s[r][4] + s[r][5] + bb;
    *(float4*)(dst + r * HH) = make_float4(y0, y1, y2, y3);
  }
}

// ---------------------------------------------------------------------------
// Kernel 2a: BN1 partial stats — grid (128 ch, 8 slices)
// ---------------------------------------------------------------------------
__global__ __launch_bounds__(256) void stats1a_kernel() {
  const int c = blockIdx.x, sl = blockIdx.y, t = threadIdx.x;
  double s = 0.0, q = 0.0;
  for (int bb = sl * 4; bb < sl * 4 + 4; ++bb) {
    const float4* p = (const float4*)(g_z + (bb * 128 + c) * PIX);
    for (int i = t; i < PIX / 4; i += 256) {
      float4 v = p[i];
      s += (double)v.x + v.y + v.z + v.w;
      q += (double)v.x * v.x + (double)v.y * v.y +
           (double)v.z * v.z + (double)v.w * v.w;
    }
  }
  __shared__ double ss[256], sq[256];
  ss[t] = s; sq[t] = q;
  __syncthreads();
  for (int o = 128; o > 0; o >>= 1) {
    if (t < o) { ss[t] += ss[t + o]; sq[t] += sq[t + o]; }
    __syncthreads();
  }
  if (t == 0) {
    g_d1[(c * 8 + sl) * 2 + 0] = ss[0];
    g_d1[(c * 8 + sl) * 2 + 1] = sq[0];
  }
}

__global__ __launch_bounds__(128) void reduce1_kernel() {
  const int c = threadIdx.x;
  double s = 0.0, q = 0.0;
#pragma unroll
  for (int sl = 0; sl < 8; ++sl) {
    s += g_d1[(c * 8 + sl) * 2 + 0];
    q += g_d1[(c * 8 + sl) * 2 + 1];
  }
  double m   = s / N1;
  double var = q / N1 - m * m;
  g_m1[c]  = (float)m;
  g_rs1[c] = rsqrtf((float)var + 1e-5f);
}

// zero BN2 accumulators (before dec each replay)
__global__ __launch_bounds__(512) void zero2_kernel() {
  const int t = threadIdx.x;
  if (t < 256) { g_sd2[t] = 0.0; g_qd2[t] = 0.0; }
}

// ---------------------------------------------------------------------------
// Threefry2x32, key (0,42), partitionable draw: x0=0, x1=j, out = o0^o1.
// ---------------------------------------------------------------------------
__device__ __forceinline__ unsigned tf_xor(unsigned j) {
  const unsigned ks0 = 0u, ks1 = 42u, ks2 = 0x1BD11BDAu ^ 42u;
  unsigned x0 = 0u + ks0;
  unsigned x1 = j  + ks1;
#define TFRND(r) { x0 += x1; x1 = __funnelshift_l(x1, x1, r); x1 ^= x0; }
  TFRND(13) TFRND(15) TFRND(26) TFRND(6)
  x0 += ks1; x1 += ks2 + 1u;
  TFRND(17) TFRND(29) TFRND(16) TFRND(24)
  x0 += ks2; x1 += ks0 + 2u;
  TFRND(13) TFRND(15) TFRND(26) TFRND(6)
  x0 += ks0; x1 += ks1 + 3u;
  TFRND(17) TFRND(29) TFRND(16) TFRND(24)
  x0 += ks1; x1 += ks2 + 4u;
  TFRND(13) TFRND(15) TFRND(26) TFRND(6)
  x0 += ks2; x1 += ks0 + 5u;
#undef TFRND
  return x0 ^ x1;
}

// ---------------------------------------------------------------------------
// Kernel 3: BN1 apply + sigmoid + quantize + BEC (in place on g_z)
// ---------------------------------------------------------------------------
__global__ __launch_bounds__(256) void bec_kernel(
    const float* __restrict__ nu, const float* __restrict__ g1,
    const float* __restrict__ be1) {
  const int e = blockIdx.x * 256 + threadIdx.x;
  const int c = (e / PIX) & 127;
  const float z = g_z[e];
  float tt = (z - g_m1[c]) * g_rs1[c] * g1[c] + be1[c];
  float s  = 0.5f * tanhf(0.5f * tt) + 0.5f;
  float r  = rintf(s * 256.0f);
  if (r >= 256.0f) r -= 256.0f;
  const unsigned xb = (unsigned)r;

  const float q = 1.0f - nu[0] * 0.5f;
  unsigned mask = 0u;
#pragma unroll
  for (int k = 0; k < 8; ++k) {
    unsigned bits = tf_xor((unsigned)(k * EZ + e));
    float u = __uint_as_float((bits >> 9) | 0x3f800000u) - 1.0f;
    if (u < q) mask |= (1u << k);
  }
  float outv = ((float)(xb & mask) + (255.0f - (float)mask) / 2.0f) / 255.0f;
  g_z[e] = outv;
}

// ---------------------------------------------------------------------------
// Kernel 4: ConvTranspose2d(k2,s2) 4-tap GEMM + FUSED BN2 partial stats.
// ---------------------------------------------------------------------------
__global__ __launch_bounds__(256) void dec_kernel(
    const float* __restrict__ w4, const float* __restrict__ b4,
    float* __restrict__ out) {
  __shared__ float4 ws4[16 * 64];
  __shared__ float4 hs4[16 * 16];
  const int t = threadIdx.x;
  const int bp = blockIdx.x;
  const int b = bp / 49;
  const int pixb = (bp % 49) * 64;
  const int cb = blockIdx.y * 64;
  const int pgrp = t & 7;
  const int cgrp = t >> 3;

  float acc[64];
#pragma unroll
  for (int i = 0; i < 64; ++i) acc[i] = 0.f;

  const float4* w44 = (const float4*)w4;
  const float4* gz4 = (const float4*)g_z;

  for (int hc0 = 0; hc0 < 128; hc0 += 16) {
    __syncthreads();
#pragma unroll
    for (int i = 0; i < 4; ++i) {
      int idx = t + i * 256;
      int hh = idx >> 6, cl = idx & 63;
      ws4[idx] = w44[(hc0 + hh) * 256 + cb + cl];
    }
    {
      int hh = t >> 4, p4 = t & 15;
      hs4[t] = gz4[((b * 128 + hc0 + hh) * PIX + pixb) / 4 + p4];
    }
    __syncthreads();
#pragma unroll
    for (int hh = 0; hh < 16; ++hh) {
      const float4 h0 = hs4[hh * 16 + pgrp * 2];
      const float4 h1 = hs4[hh * 16 + pgrp * 2 + 1];
      const float4 wa = ws4[hh * 64 + cgrp * 2];
      const float4 wb = ws4[hh * 64 + cgrp * 2 + 1];
      const float hv[8] = {h0.x, h0.y, h0.z, h0.w, h1.x, h1.y, h1.z, h1.w};
#pragma unroll
      for (int pp = 0; pp < 8; ++pp) {
        acc[pp * 4 + 0] += hv[pp] * wa.x;
        acc[pp * 4 + 1] += hv[pp] * wa.y;
        acc[pp * 4 + 2] += hv[pp] * wa.z;
        acc[pp * 4 + 3] += hv[pp] * wa.w;
        acc[32 + pp * 4 + 0] += hv[pp] * wb.x;
        acc[32 + pp * 4 + 1] += hv[pp] * wb.y;
        acc[32 + pp * 4 + 2] += hv[pp] * wb.z;
        acc[32 + pp * 4 + 3] += hv[pp] * wb.w;
      }
    }
  }

  float sums[2] = {0.f, 0.f}, sumq[2] = {0.f, 0.f};
#pragma unroll
  for (int cc = 0; cc < 2; ++cc) {
    const int c = cb + cgrp * 2 + cc;
    const float bb = b4[c];
#pragma unroll
    for (int pp = 0; pp < 8; ++pp) {
      const int pix = pixb + pgrp * 8 + pp;
      const int ih = pix / HH, iw = pix % HH;
      float* dst = out + ((b * 256 + c) * OHH + 2 * ih) * OHH + 2 * iw;
      float v0 = acc[cc * 32 + pp * 4 + 0] + bb;
      float v1 = acc[cc * 32 + pp * 4 + 1] + bb;
      float v2 = acc[cc * 32 + pp * 4 + 2] + bb;
      float v3 = acc[cc * 32 + pp * 4 + 3] + bb;
      *(float2*)dst = make_float2(v0, v1);
      *(float2*)(dst + OHH) = make_float2(v2, v3);
      sums[cc] += v0 + v1 + v2 + v3;
      sumq[cc] += v0 * v0 + v1 * v1 + v2 * v2 + v3 * v3;
    }
  }
#pragma unroll
  for (int off = 1; off < 8; off <<= 1) {
    sums[0] += __shfl_xor_sync(0xffffffffu, sums[0], off);
    sumq[0] += __shfl_xor_sync(0xffffffffu, sumq[0], off);
    sums[1] += __shfl_xor_sync(0xffffffffu, sums[1], off);
    sumq[1] += __shfl_xor_sync(0xffffffffu, sumq[1], off);
  }
  if (pgrp == 0) {
    const int c0 = cb + cgrp * 2;
    atomicAdd(&g_sd2[c0],     (double)sums[0]);
    atomicAdd(&g_qd2[c0],     (double)sumq[0]);
    atomicAdd(&g_sd2[c0 + 1], (double)sums[1]);
    atomicAdd(&g_qd2[c0 + 1], (double)sumq[1]);
  }
}

// ---------------------------------------------------------------------------
// Kernel 6: BN2 apply (stats inline from accumulators) + relu, in place
// ---------------------------------------------------------------------------
__global__ __launch_bounds__(256) void bn2_kernel(
    const float* __restrict__ g2, const float* __restrict__ be2,
    float* __restrict__ out) {
  const int i = blockIdx.x * 256 + threadIdx.x;
  const int c = (i / (OPIX / 4)) & 255;
  const double inv = 1.0 / (double)N2;
  const double md = g_sd2[c] * inv;
  const double var = g_qd2[c] * inv - md * md;
  const float m = (float)md;
  const float rs = rsqrtf((float)var + 1e-5f);
  float4 v = ((float4*)out)[i];
  const float gg = g2[c], bb = be2[c];
  v.x = fmaxf((v.x - m) * rs * gg + bb, 0.f);
  v.y = fmaxf((v.y - m) * rs * gg + bb, 0.f);
  v.z = fmaxf((v.z - m) * rs * gg + bb, 0.f);
  v.w = fmaxf((v.w - m) * rs * gg + bb, 0.f);
  ((float4*)out)[i] = v;
}

// ---------------------------------------------------------------------------
extern "C" void kernel_launch(void* const* d_in, const int* in_sizes, int n_in,
                              void* d_out, int out_size) {
  const float* x   = (const float*)d_in[0];
  const float* nu  = (const float*)d_in[1];
  const float* w1  = (const float*)d_in[2];
  const float* b1  = (const float*)d_in[3];
  const float* g1  = (const float*)d_in[4];
  const float* be1 = (const float*)d_in[5];
  const float* w4  = (const float*)d_in[6];
  const float* b4  = (const float*)d_in[7];
  const float* g2  = (const float*)d_in[8];
  const float* be2 = (const float*)d_in[9];
  float* out = (float*)d_out;

  uT_kernel<<<(KUSE * 128 + 255) / 256, 256>>>(w1);
  vT_kernel<<<dim3(KUSE, 32), 256>>>(x, nu);
  wgemm_kernel<<<dim3(NT / 128, 36), 256>>>();
  oT_kernel<<<(BB * 128 * TPB) / 256, 256>>>(b1);
  stats1a_kernel<<<dim3(128, 8), 256>>>();
  reduce1_kernel<<<1, 128>>>();
  zero2_kernel<<<1, 512>>>();
  bec_kernel<<<EZ / 256, 256>>>(nu, g1, be1);
  dec_kernel<<<dim3(32 * 49, 4), 256>>>(w4, b4, out);
  bn2_kernel<<<out_size / 4 / 256, 256>>>(g2, be2, out);
}

// round 15
// speedup vs baseline: 1.1587x; 1.0585x over previous
#include <cuda_runtime.h>
#include <cstdint>

#define BB 32
#define HH 56
#define HC 128
#define CC 256
#define PIX (HH*HH)          // 3136
#define EZ (BB*HC*PIX)       // 12845056
#define N1 (BB*PIX)          // 100352
#define OHH 112
#define OPIX (OHH*OHH)       // 12544
#define N2 (BB*OPIX)         // 401408

#define KP 272               // padded K stride (257 used; pad for chunk-16 prefetch)
#define KUSE 257
#define TPB 196              // 14x14 tiles per batch (F(4x4))
#define NT (BB*TPB)          // 6272 tiles

__device__ __align__(128) float g_z[EZ];            // conv1 out -> BEC output h
__device__ __align__(128) float g_U[36*KP*128];     // transformed weights [p][ic][oc]
__device__ __align__(128) float g_V[36*KP*NT];      // transformed inputs  [p][ic][T] (zero-init pads)
__device__ __align__(128) float g_M[36*128*NT];     // products [p][oc][T]
__device__ double g_sd1[128], g_qd1[128];           // BN1 atomic accumulators
__device__ double g_sd2[256], g_qd2[256];           // BN2 atomic accumulators
__device__ float g_m1[HC], g_rs1[HC];

#define CPASYNC16(dst, src) \
  asm volatile("cp.async.ca.shared.global [%0], [%1], 16;" :: "r"(dst), "l"(src))
#define CPCOMMIT() asm volatile("cp.async.commit_group;" ::: "memory")
#define CPWAIT0()  asm volatile("cp.async.wait_group 0;" ::: "memory")

// ---------------------------------------------------------------------------
// Kernel Z: zero all BN accumulators (start of every replay)
// ---------------------------------------------------------------------------
__global__ __launch_bounds__(256) void zero_kernel() {
  const int t = threadIdx.x;
  if (t < 128) { g_sd1[t] = 0.0; g_qd1[t] = 0.0; }
  g_sd2[t] = 0.0; g_qd2[t] = 0.0;
}

// ---------------------------------------------------------------------------
// Kernel A: weight transform  U = G g G^T  for F(4x4,3x3)
// ---------------------------------------------------------------------------
__global__ __launch_bounds__(256) void uT_kernel(const float* __restrict__ w1) {
  int i = blockIdx.x * 256 + threadIdx.x;
  if (i >= KUSE * 128) return;
  int oc = i & 127, ic = i >> 7;
  float g[3][3];
#pragma unroll
  for (int r = 0; r < 3; ++r)
#pragma unroll
    for (int c = 0; c < 3; ++c) g[r][c] = w1[oc * 2313 + ic * 9 + r * 3 + c];
  float t[6][3];
#pragma unroll
  for (int c = 0; c < 3; ++c) {
    t[0][c] = 0.25f * g[0][c];
    t[1][c] = (-1.f/6.f) * (g[0][c] + g[1][c] + g[2][c]);
    t[2][c] = (1.f/6.f) * (-g[0][c] + g[1][c] - g[2][c]);
    t[3][c] = (1.f/24.f) * g[0][c] + (1.f/12.f) * g[1][c] + (1.f/6.f) * g[2][c];
    t[4][c] = (1.f/24.f) * g[0][c] - (1.f/12.f) * g[1][c] + (1.f/6.f) * g[2][c];
    t[5][c] = g[2][c];
  }
  float u[6][6];
#pragma unroll
  for (int r = 0; r < 6; ++r) {
    u[r][0] = 0.25f * t[r][0];
    u[r][1] = (-1.f/6.f) * (t[r][0] + t[r][1] + t[r][2]);
    u[r][2] = (1.f/6.f) * (-t[r][0] + t[r][1] - t[r][2]);
    u[r][3] = (1.f/24.f) * t[r][0] + (1.f/12.f) * t[r][1] + (1.f/6.f) * t[r][2];
    u[r][4] = (1.f/24.f) * t[r][0] - (1.f/12.f) * t[r][1] + (1.f/6.f) * t[r][2];
    u[r][5] = t[r][2];
  }
#pragma unroll
  for (int p = 0; p < 36; ++p)
    g_U[(p * KP + ic) * 128 + oc] = u[p / 6][p % 6];
}

// ---------------------------------------------------------------------------
// Kernel B: input transform  V = B^T d B  per 4x4-output tile (6x6 input).
// ---------------------------------------------------------------------------
__global__ __launch_bounds__(256) void vT_kernel(
    const float* __restrict__ x, const float* __restrict__ nu) {
  __shared__ float sp[58 * 58];
  const int ic = blockIdx.x, b = blockIdx.y, t = threadIdx.x;
  for (int i = t; i < 58 * 58; i += 256) sp[i] = 0.f;
  __syncthreads();
  if (ic < 256) {
    const float* xp = x + ((long)b * 256 + ic) * PIX;
    for (int i = t; i < PIX; i += 256) {
      int r = i / 56, c = i - r * 56;
      sp[(r + 1) * 58 + c + 1] = xp[i];
    }
  } else {
    const float nf = nu[0] * 0.5f;
    for (int i = t; i < PIX; i += 256) {
      int r = i / 56, c = i - r * 56;
      sp[(r + 1) * 58 + c + 1] = nf;
    }
  }
  __syncthreads();

  const int base = ic * NT + b * TPB;
  for (int tile = t; tile < TPB; tile += 256) {
    const int ty = tile / 14, tx = tile - ty * 14;
    float d[6][6];
#pragma unroll
    for (int r = 0; r < 6; ++r)
#pragma unroll
      for (int c = 0; c < 6; ++c) d[r][c] = sp[(4 * ty + r) * 58 + 4 * tx + c];
    float td[6][6];
#pragma unroll
    for (int c = 0; c < 6; ++c) {
      td[0][c] = 4.f * d[0][c] - 5.f * d[2][c] + d[4][c];
      td[1][c] = -4.f * d[1][c] - 4.f * d[2][c] + d[3][c] + d[4][c];
      td[2][c] = 4.f * d[1][c] - 4.f * d[2][c] - d[3][c] + d[4][c];
      td[3][c] = -2.f * d[1][c] - d[2][c] + 2.f * d[3][c] + d[4][c];
      td[4][c] = 2.f * d[1][c] - d[2][c] - 2.f * d[3][c] + d[4][c];
      td[5][c] = 4.f * d[1][c] - 5.f * d[3][c] + d[5][c];
    }
    float v[6][6];
#pragma unroll
    for (int r = 0; r < 6; ++r) {
      v[r][0] = 4.f * td[r][0] - 5.f * td[r][2] + td[r][4];
      v[r][1] = -4.f * td[r][1] - 4.f * td[r][2] + td[r][3] + td[r][4];
      v[r][2] = 4.f * td[r][1] - 4.f * td[r][2] - td[r][3] + td[r][4];
      v[r][3] = -2.f * td[r][1] - td[r][2] + 2.f * td[r][3] + td[r][4];
      v[r][4] = 2.f * td[r][1] - td[r][2] - 2.f * td[r][3] + td[r][4];
      v[r][5] = 4.f * td[r][1] - 5.f * td[r][3] + td[r][5];
    }
#pragma unroll
    for (int p = 0; p < 36; ++p)
      g_V[p * (KP * NT) + base + tile] = v[p / 6][p % 6];
  }
}

// ---------------------------------------------------------------------------
// Kernel C: 36 batched GEMMs  M_p[128 oc][NT] = U_p[128][K=257] * V_p[257][NT].
// cp.async double-buffered K-chunks of 16 (17 syncs), peeled k=256 step.
// ---------------------------------------------------------------------------
__global__ __launch_bounds__(256) void wgemm_kernel() {
  __shared__ float sU[2][16 * 128];
  __shared__ float sV[2][16 * 128];
  const int t = threadIdx.x;
  const int og = t >> 4, tg = t & 15;
  const int p = blockIdx.y;
  const int Tb = blockIdx.x * 128;
  const int rA = t >> 5, cA = (t & 31) * 4;

  const float* Ug = g_U + p * (KP * 128);
  const float* Vg = g_V + (long)p * (KP * NT);

  const uint32_t sUb = (uint32_t)__cvta_generic_to_shared(&sU[0][0]);
  const uint32_t sVb = (uint32_t)__cvta_generic_to_shared(&sV[0][0]);

#define STAGE(buf, ch) do {                                                   \
    const int kb_ = (ch) * 16;                                                \
    uint32_t du_ = sUb + ((buf) * 2048 + rA * 128 + cA) * 4;                  \
    CPASYNC16(du_,        Ug + (kb_ + rA) * 128 + cA);                        \
    CPASYNC16(du_ + 4096, Ug + (kb_ + rA + 8) * 128 + cA);                    \
    uint32_t dv_ = sVb + ((buf) * 2048 + rA * 128 + cA) * 4;                  \
    CPASYNC16(dv_,        Vg + (long)(kb_ + rA) * NT + Tb + cA);              \
    CPASYNC16(dv_ + 4096, Vg + (long)(kb_ + rA + 8) * NT + Tb + cA);          \
    CPCOMMIT();                                                               \
  } while (0)

  STAGE(0, 0);
  CPWAIT0();
  __syncthreads();

  float acc[64];
#pragma unroll
  for (int i = 0; i < 64; ++i) acc[i] = 0.f;

  for (int ch = 0; ch < 16; ++ch) {
    const int cur = ch & 1, nxt = cur ^ 1;
    STAGE(nxt, ch + 1);
#pragma unroll
    for (int k = 0; k < 16; ++k) {
      const float4 ua = *(const float4*)&sU[cur][k * 128 + og * 8];
      const float4 ub = *(const float4*)&sU[cur][k * 128 + og * 8 + 4];
      const float4 va = *(const float4*)&sV[cur][k * 128 + tg * 8];
      const float4 vb = *(const float4*)&sV[cur][k * 128 + tg * 8 + 4];
      const float uu[8] = {ua.x, ua.y, ua.z, ua.w, ub.x, ub.y, ub.z, ub.w};
      const float vv[8] = {va.x, va.y, va.z, va.w, vb.x, vb.y, vb.z, vb.w};
#pragma unroll
      for (int j = 0; j < 8; ++j)
#pragma unroll
        for (int i = 0; i < 8; ++i) acc[j * 8 + i] += uu[j] * vv[i];
    }
    CPWAIT0();
    __syncthreads();
  }
  // peeled final step: k = 256 = row 0 of chunk 16 (buffer 0)
  {
    const float4 ua = *(const float4*)&sU[0][og * 8];
    const float4 ub = *(const float4*)&sU[0][og * 8 + 4];
    const float4 va = *(const float4*)&sV[0][tg * 8];
    const float4 vb = *(const float4*)&sV[0][tg * 8 + 4];
    const float uu[8] = {ua.x, ua.y, ua.z, ua.w, ub.x, ub.y, ub.z, ub.w};
    const float vv[8] = {va.x, va.y, va.z, va.w, vb.x, vb.y, vb.z, vb.w};
#pragma unroll
    for (int j = 0; j < 8; ++j)
#pragma unroll
      for (int i = 0; i < 8; ++i) acc[j * 8 + i] += uu[j] * vv[i];
  }
#undef STAGE

#pragma unroll
  for (int j = 0; j < 8; ++j) {
    float* dst = g_M + ((long)p * 128 + og * 8 + j) * NT + Tb + tg * 8;
    ((float4*)dst)[0] = make_float4(acc[j*8+0], acc[j*8+1], acc[j*8+2], acc[j*8+3]);
    ((float4*)dst)[1] = make_float4(acc[j*8+4], acc[j*8+5], acc[j*8+6], acc[j*8+7]);
  }
}

// ---------------------------------------------------------------------------
// Kernel D: output transform  Y = A^T M A  (+bias) -> g_z  + FUSED BN1 stats.
// Per-thread fp32 partials -> segmented warp-shfl reduce (<=2 oc segments
// per warp) -> one global double atomicAdd pair per segment leader.
// ---------------------------------------------------------------------------
__global__ __launch_bounds__(256) void oT_kernel(const float* __restrict__ b1) {
  const int t = threadIdx.x;
  const int lane = t & 31;
  const int i = blockIdx.x * 256 + t;
  const int tile = i % TPB;
  const int boc = i / TPB;
  const int oc = boc & 127, b = boc >> 7;
  const int Ti = b * TPB + tile;

  float m[6][6];
#pragma unroll
  for (int p = 0; p < 36; ++p)
    m[p / 6][p % 6] = g_M[((long)p * 128 + oc) * NT + Ti];

  float s[4][6];
#pragma unroll
  for (int c = 0; c < 6; ++c) {
    s[0][c] = m[0][c] + m[1][c] + m[2][c] + m[3][c] + m[4][c];
    s[1][c] = m[1][c] - m[2][c] + 2.f * m[3][c] - 2.f * m[4][c];
    s[2][c] = m[1][c] + m[2][c] + 4.f * m[3][c] + 4.f * m[4][c];
    s[3][c] = m[1][c] - m[2][c] + 8.f * m[3][c] - 8.f * m[4][c] + m[5][c];
  }
  const float bb = b1[oc];
  const int ty = tile / 14, tx = tile - ty * 14;
  float* dst = g_z + ((b * 128 + oc) * HH + 4 * ty) * HH + 4 * tx;
  float fs = 0.f, fq = 0.f;
#pragma unroll
  for (int r = 0; r < 4; ++r) {
    float y0 = s[r][0] + s[r][1] + s[r][2] + s[r][3] + s[r][4] + bb;
    float y1 = s[r][1] - s[r][2] + 2.f * s[r][3] - 2.f * s[r][4] + bb;
    float y2 = s[r][1] + s[r][2] + 4.f * s[r][3] + 4.f * s[r][4] + bb;
    float y3 = s[r][1] - s[r][2] + 8.f * s[r][3] - 8.f * s[r][4] + s[r][5] + bb;
    *(float4*)(dst + r * HH) = make_float4(y0, y1, y2, y3);
    fs += y0 + y1 + y2 + y3;
    fq += y0 * y0 + y1 * y1 + y2 * y2 + y3 * y3;
  }
  // segmented reduction over lanes with equal boc (contiguous segments)
  const unsigned grp = __match_any_sync(0xffffffffu, boc);
#pragma unroll
  for (int off = 16; off; off >>= 1) {
    float as = __shfl_down_sync(0xffffffffu, fs, off);
    float aq = __shfl_down_sync(0xffffffffu, fq, off);
    const int src = lane + off;
    if (src < 32 && ((grp >> src) & 1u)) { fs += as; fq += aq; }
  }
  if (lane == (int)(__ffs(grp) - 1)) {
    atomicAdd(&g_sd1[oc], (double)fs);
    atomicAdd(&g_qd1[oc], (double)fq);
  }
}

// tiny: finalize BN1 mean/rsqrt from atomic accumulators
__global__ __launch_bounds__(128) void reduce1_kernel() {
  const int c = threadIdx.x;
  double m   = g_sd1[c] / N1;
  double var = g_qd1[c] / N1 - m * m;
  g_m1[c]  = (float)m;
  g_rs1[c] = rsqrtf((float)var + 1e-5f);
}

// ---------------------------------------------------------------------------
// Threefry2x32, key (0,42), partitionable draw: x0=0, x1=j, out = o0^o1.
// ---------------------------------------------------------------------------
__device__ __forceinline__ unsigned tf_xor(unsigned j) {
  const unsigned ks0 = 0u, ks1 = 42u, ks2 = 0x1BD11BDAu ^ 42u;
  unsigned x0 = 0u + ks0;
  unsigned x1 = j  + ks1;
#define TFRND(r) { x0 += x1; x1 = __funnelshift_l(x1, x1, r); x1 ^= x0; }
  TFRND(13) TFRND(15) TFRND(26) TFRND(6)
  x0 += ks1; x1 += ks2 + 1u;
  TFRND(17) TFRND(29) TFRND(16) TFRND(24)
  x0 += ks2; x1 += ks0 + 2u;
  TFRND(13) TFRND(15) TFRND(26) TFRND(6)
  x0 += ks0; x1 += ks1 + 3u;
  TFRND(17) TFRND(29) TFRND(16) TFRND(24)
  x0 += ks1; x1 += ks2 + 4u;
  TFRND(13) TFRND(15) TFRND(26) TFRND(6)
  x0 += ks2; x1 += ks0 + 5u;
#undef TFRND
  return x0 ^ x1;
}

// ---------------------------------------------------------------------------
// Kernel 3: BN1 apply + sigmoid + quantize + BEC (in place on g_z)
// ---------------------------------------------------------------------------
__global__ __launch_bounds__(256) void bec_kernel(
    const float* __restrict__ nu, const float* __restrict__ g1,
    const float* __restrict__ be1) {
  const int e = blockIdx.x * 256 + threadIdx.x;
  const int c = (e / PIX) & 127;
  const float z = g_z[e];
  float tt = (z - g_m1[c]) * g_rs1[c] * g1[c] + be1[c];
  float s  = 0.5f * tanhf(0.5f * tt) + 0.5f;
  float r  = rintf(s * 256.0f);
  if (r >= 256.0f) r -= 256.0f;
  const unsigned xb = (unsigned)r;

  const float q = 1.0f - nu[0] * 0.5f;
  unsigned mask = 0u;
#pragma unroll
  for (int k = 0; k < 8; ++k) {
    unsigned bits = tf_xor((unsigned)(k * EZ + e));
    float u = __uint_as_float((bits >> 9) | 0x3f800000u) - 1.0f;
    if (u < q) mask |= (1u << k);
  }
  float outv = ((float)(xb & mask) + (255.0f - (float)mask) / 2.0f) / 255.0f;
  g_z[e] = outv;
}

// ---------------------------------------------------------------------------
// Kernel 4: ConvTranspose2d(k2,s2) 4-tap GEMM + FUSED BN2 partial stats.
// ---------------------------------------------------------------------------
__global__ __launch_bounds__(256) void dec_kernel(
    const float* __restrict__ w4, const float* __restrict__ b4,
    float* __restrict__ out) {
  __shared__ float4 ws4[16 * 64];
  __shared__ float4 hs4[16 * 16];
  const int t = threadIdx.x;
  const int bp = blockIdx.x;
  const int b = bp / 49;
  const int pixb = (bp % 49) * 64;
  const int cb = blockIdx.y * 64;
  const int pgrp = t & 7;
  const int cgrp = t >> 3;

  float acc[64];
#pragma unroll
  for (int i = 0; i < 64; ++i) acc[i] = 0.f;

  const float4* w44 = (const float4*)w4;
  const float4* gz4 = (const float4*)g_z;

  for (int hc0 = 0; hc0 < 128; hc0 += 16) {
    __syncthreads();
#pragma unroll
    for (int i = 0; i < 4; ++i) {
      int idx = t + i * 256;
      int hh = idx >> 6, cl = idx & 63;
      ws4[idx] = w44[(hc0 + hh) * 256 + cb + cl];
    }
    {
      int hh = t >> 4, p4 = t & 15;
      hs4[t] = gz4[((b * 128 + hc0 + hh) * PIX + pixb) / 4 + p4];
    }
    __syncthreads();
#pragma unroll
    for (int hh = 0; hh < 16; ++hh) {
      const float4 h0 = hs4[hh * 16 + pgrp * 2];
      const float4 h1 = hs4[hh * 16 + pgrp * 2 + 1];
      const float4 wa = ws4[hh * 64 + cgrp * 2];
      const float4 wb = ws4[hh * 64 + cgrp * 2 + 1];
      const float hv[8] = {h0.x, h0.y, h0.z, h0.w, h1.x, h1.y, h1.z, h1.w};
#pragma unroll
      for (int pp = 0; pp < 8; ++pp) {
        acc[pp * 4 + 0] += hv[pp] * wa.x;
        acc[pp * 4 + 1] += hv[pp] * wa.y;
        acc[pp * 4 + 2] += hv[pp] * wa.z;
        acc[pp * 4 + 3] += hv[pp] * wa.w;
        acc[32 + pp * 4 + 0] += hv[pp] * wb.x;
        acc[32 + pp * 4 + 1] += hv[pp] * wb.y;
        acc[32 + pp * 4 + 2] += hv[pp] * wb.z;
        acc[32 + pp * 4 + 3] += hv[pp] * wb.w;
      }
    }
  }

  float sums[2] = {0.f, 0.f}, sumq[2] = {0.f, 0.f};
#pragma unroll
  for (int cc = 0; cc < 2; ++cc) {
    const int c = cb + cgrp * 2 + cc;
    const float bb = b4[c];
#pragma unroll
    for (int pp = 0; pp < 8; ++pp) {
      const int pix = pixb + pgrp * 8 + pp;
      const int ih = pix / HH, iw = pix % HH;
      float* dst = out + ((b * 256 + c) * OHH + 2 * ih) * OHH + 2 * iw;
      float v0 = acc[cc * 32 + pp * 4 + 0] + bb;
      float v1 = acc[cc * 32 + pp * 4 + 1] + bb;
      float v2 = acc[cc * 32 + pp * 4 + 2] + bb;
      float v3 = acc[cc * 32 + pp * 4 + 3] + bb;
      *(float2*)dst = make_float2(v0, v1);
      *(float2*)(dst + OHH) = make_float2(v2, v3);
      sums[cc] += v0 + v1 + v2 + v3;
      sumq[cc] += v0 * v0 + v1 * v1 + v2 * v2 + v3 * v3;
    }
  }
#pragma unroll
  for (int off = 1; off < 8; off <<= 1) {
    sums[0] += __shfl_xor_sync(0xffffffffu, sums[0], off);
    sumq[0] += __shfl_xor_sync(0xffffffffu, sumq[0], off);
    sums[1] += __shfl_xor_sync(0xffffffffu, sums[1], off);
    sumq[1] += __shfl_xor_sync(0xffffffffu, sumq[1], off);
  }
  if (pgrp == 0) {
    const int c0 = cb + cgrp * 2;
    atomicAdd(&g_sd2[c0],     (double)sums[0]);
    atomicAdd(&g_qd2[c0],     (double)sumq[0]);
    atomicAdd(&g_sd2[c0 + 1], (double)sums[1]);
    atomicAdd(&g_qd2[c0 + 1], (double)sumq[1]);
  }
}

// ---------------------------------------------------------------------------
// Kernel 6: BN2 apply (stats inline from accumulators) + relu, in place
// ---------------------------------------------------------------------------
__global__ __launch_bounds__(256) void bn2_kernel(
    const float* __restrict__ g2, const float* __restrict__ be2,
    float* __restrict__ out) {
  const int i = blockIdx.x * 256 + threadIdx.x;
  const int c = (i / (OPIX / 4)) & 255;
  const double inv = 1.0 / (double)N2;
  const double md = g_sd2[c] * inv;
  const double var = g_qd2[c] * inv - md * md;
  const float m = (float)md;
  const float rs = rsqrtf((float)var + 1e-5f);
  float4 v = ((float4*)out)[i];
  const float gg = g2[c], bb = be2[c];
  v.x = fmaxf((v.x - m) * rs * gg + bb, 0.f);
  v.y = fmaxf((v.y - m) * rs * gg + bb, 0.f);
  v.z = fmaxf((v.z - m) * rs * gg + bb, 0.f);
  v.w = fmaxf((v.w - m) * rs * gg + bb, 0.f);
  ((float4*)out)[i] = v;
}

// ---------------------------------------------------------------------------
extern "C" void kernel_launch(void* const* d_in, const int* in_sizes, int n_in,
                              void* d_out, int out_size) {
  const float* x   = (const float*)d_in[0];
  const float* nu  = (const float*)d_in[1];
  const float* w1  = (const float*)d_in[2];
  const float* b1  = (const float*)d_in[3];
  const float* g1  = (const float*)d_in[4];
  const float* be1 = (const float*)d_in[5];
  const float* w4  = (const float*)d_in[6];
  const float* b4  = (const float*)d_in[7];
  const float* g2  = (const float*)d_in[8];
  const float* be2 = (const float*)d_in[9];
  float* out = (float*)d_out;

  zero_kernel<<<1, 256>>>();
  uT_kernel<<<(KUSE * 128 + 255) / 256, 256>>>(w1);
  vT_kernel<<<dim3(KUSE, 32), 256>>>(x, nu);
  wgemm_kernel<<<dim3(NT / 128, 36), 256>>>();
  oT_kernel<<<(BB * 128 * TPB) / 256, 256>>>(b1);
  reduce1_kernel<<<1, 128>>>();
  bec_kernel<<<EZ / 256, 256>>>(nu, g1, be1);
  dec_kernel<<<dim3(32 * 49, 4), 256>>>(w4, b4, out);
  bn2_kernel<<<out_size / 4 / 256, 256>>>(g2, be2, out);
}

// round 16
// speedup vs baseline: 1.1617x; 1.0025x over previous
#include <cuda_runtime.h>
#include <cstdint>

#define BB 32
#define HH 56
#define HC 128
#define CC 256
#define PIX (HH*HH)          // 3136
#define EZ (BB*HC*PIX)       // 12845056
#define N1 (BB*PIX)          // 100352
#define OHH 112
#define OPIX (OHH*OHH)       // 12544
#define N2 (BB*OPIX)         // 401408

#define KP 288               // padded K stride (257 used; pad for chunk-32 prefetch)
#define KUSE 257
#define TPB 196              // 14x14 tiles per batch (F(4x4))
#define NT (BB*TPB)          // 6272 tiles

__device__ __align__(128) float g_z[EZ];            // conv1 out -> BEC output h
__device__ __align__(128) float g_U[36*KP*128];     // transformed weights [p][ic][oc]
__device__ __align__(128) float g_V[36*KP*NT];      // transformed inputs  [p][ic][T] (zero-init pads)
__device__ __align__(128) float g_M[36*128*NT];     // products [p][oc][T]
__device__ double g_sd1[128], g_qd1[128];           // BN1 atomic accumulators
__device__ double g_sd2[256], g_qd2[256];           // BN2 atomic accumulators
__device__ float g_m1[HC], g_rs1[HC];

#define CPASYNC16(dst, src) \
  asm volatile("cp.async.ca.shared.global [%0], [%1], 16;" :: "r"(dst), "l"(src))
#define CPCOMMIT() asm volatile("cp.async.commit_group;" ::: "memory")
#define CPWAIT0()  asm volatile("cp.async.wait_group 0;" ::: "memory")

// ---------------------------------------------------------------------------
// Kernel Z: zero all BN accumulators (start of every replay)
// ---------------------------------------------------------------------------
__global__ __launch_bounds__(256) void zero_kernel() {
  const int t = threadIdx.x;
  if (t < 128) { g_sd1[t] = 0.0; g_qd1[t] = 0.0; }
  g_sd2[t] = 0.0; g_qd2[t] = 0.0;
}

// ---------------------------------------------------------------------------
// Kernel A: weight transform  U = G g G^T  for F(4x4,3x3)
// ---------------------------------------------------------------------------
__global__ __launch_bounds__(256) void uT_kernel(const float* __restrict__ w1) {
  int i = blockIdx.x * 256 + threadIdx.x;
  if (i >= KUSE * 128) return;
  int oc = i & 127, ic = i >> 7;
  float g[3][3];
#pragma unroll
  for (int r = 0; r < 3; ++r)
#pragma unroll
    for (int c = 0; c < 3; ++c) g[r][c] = w1[oc * 2313 + ic * 9 + r * 3 + c];
  float t[6][3];
#pragma unroll
  for (int c = 0; c < 3; ++c) {
    t[0][c] = 0.25f * g[0][c];
    t[1][c] = (-1.f/6.f) * (g[0][c] + g[1][c] + g[2][c]);
    t[2][c] = (1.f/6.f) * (-g[0][c] + g[1][c] - g[2][c]);
    t[3][c] = (1.f/24.f) * g[0][c] + (1.f/12.f) * g[1][c] + (1.f/6.f) * g[2][c];
    t[4][c] = (1.f/24.f) * g[0][c] - (1.f/12.f) * g[1][c] + (1.f/6.f) * g[2][c];
    t[5][c] = g[2][c];
  }
  float u[6][6];
#pragma unroll
  for (int r = 0; r < 6; ++r) {
    u[r][0] = 0.25f * t[r][0];
    u[r][1] = (-1.f/6.f) * (t[r][0] + t[r][1] + t[r][2]);
    u[r][2] = (1.f/6.f) * (-t[r][0] + t[r][1] - t[r][2]);
    u[r][3] = (1.f/24.f) * t[r][0] + (1.f/12.f) * t[r][1] + (1.f/6.f) * t[r][2];
    u[r][4] = (1.f/24.f) * t[r][0] - (1.f/12.f) * t[r][1] + (1.f/6.f) * t[r][2];
    u[r][5] = t[r][2];
  }
#pragma unroll
  for (int p = 0; p < 36; ++p)
    g_U[(p * KP + ic) * 128 + oc] = u[p / 6][p % 6];
}

// ---------------------------------------------------------------------------
// Kernel B: input transform  V = B^T d B  per 4x4-output tile (6x6 input).
// ---------------------------------------------------------------------------
__global__ __launch_bounds__(256) void vT_kernel(
    const float* __restrict__ x, const float* __restrict__ nu) {
  __shared__ float sp[58 * 58];
  const int ic = blockIdx.x, b = blockIdx.y, t = threadIdx.x;
  for (int i = t; i < 58 * 58; i += 256) sp[i] = 0.f;
  __syncthreads();
  if (ic < 256) {
    const float* xp = x + ((long)b * 256 + ic) * PIX;
    for (int i = t; i < PIX; i += 256) {
      int r = i / 56, c = i - r * 56;
      sp[(r + 1) * 58 + c + 1] = xp[i];
    }
  } else {
    const float nf = nu[0] * 0.5f;
    for (int i = t; i < PIX; i += 256) {
      int r = i / 56, c = i - r * 56;
      sp[(r + 1) * 58 + c + 1] = nf;
    }
  }
  __syncthreads();

  const int base = ic * NT + b * TPB;
  for (int tile = t; tile < TPB; tile += 256) {
    const int ty = tile / 14, tx = tile - ty * 14;
    float d[6][6];
#pragma unroll
    for (int r = 0; r < 6; ++r)
#pragma unroll
      for (int c = 0; c < 6; ++c) d[r][c] = sp[(4 * ty + r) * 58 + 4 * tx + c];
    float td[6][6];
#pragma unroll
    for (int c = 0; c < 6; ++c) {
      td[0][c] = 4.f * d[0][c] - 5.f * d[2][c] + d[4][c];
      td[1][c] = -4.f * d[1][c] - 4.f * d[2][c] + d[3][c] + d[4][c];
      td[2][c] = 4.f * d[1][c] - 4.f * d[2][c] - d[3][c] + d[4][c];
      td[3][c] = -2.f * d[1][c] - d[2][c] + 2.f * d[3][c] + d[4][c];
      td[4][c] = 2.f * d[1][c] - d[2][c] - 2.f * d[3][c] + d[4][c];
      td[5][c] = 4.f * d[1][c] - 5.f * d[3][c] + d[5][c];
    }
    float v[6][6];
#pragma unroll
    for (int r = 0; r < 6; ++r) {
      v[r][0] = 4.f * td[r][0] - 5.f * td[r][2] + td[r][4];
      v[r][1] = -4.f * td[r][1] - 4.f * td[r][2] + td[r][3] + td[r][4];
      v[r][2] = 4.f * td[r][1] - 4.f * td[r][2] - td[r][3] + td[r][4];
      v[r][3] = -2.f * td[r][1] - td[r][2] + 2.f * td[r][3] + td[r][4];
      v[r][4] = 2.f * td[r][1] - td[r][2] - 2.f * td[r][3] + td[r][4];
      v[r][5] = 4.f * td[r][1] - 5.f * td[r][3] + td[r][5];
    }
#pragma unroll
    for (int p = 0; p < 36; ++p)
      g_V[p * (KP * NT) + base + tile] = v[p / 6][p % 6];
  }
}

// ---------------------------------------------------------------------------
// Kernel C: 36 batched GEMMs  M_p[128 oc][NT] = U_p[128][K=257] * V_p[257][NT].
// cp.async double-buffered K-chunks of 32 (9 syncs), peeled k=256 step.
// Dynamic smem: sU[2][32*128] + sV[2][32*128] = 64 KB.
// Accumulation order strictly k = 0..256 ascending (bitwise-identical).
// ---------------------------------------------------------------------------
__global__ __launch_bounds__(256) void wgemm_kernel() {
  extern __shared__ float sm[];
  float* sU = sm;             // [2][32*128]
  float* sV = sm + 8192;      // [2][32*128]
  const int t = threadIdx.x;
  const int og = t >> 4, tg = t & 15;
  const int p = blockIdx.y;
  const int Tb = blockIdx.x * 128;
  const int rA = t >> 5, cA = (t & 31) * 4;   // base row 0..7, col

  const float* Ug = g_U + p * (KP * 128);
  const float* Vg = g_V + (long)p * (KP * NT);

  const uint32_t sUb = (uint32_t)__cvta_generic_to_shared(sU);
  const uint32_t sVb = (uint32_t)__cvta_generic_to_shared(sV);

  // stage chunk ch (32 k-rows) into buffer buf; 8 cp.async per thread
#define STAGE(buf, ch) do {                                                   \
    const int kb_ = (ch) * 32;                                                \
    uint32_t du_ = sUb + ((buf) * 4096 + rA * 128 + cA) * 4;                  \
    uint32_t dv_ = sVb + ((buf) * 4096 + rA * 128 + cA) * 4;                  \
    _Pragma("unroll")                                                         \
    for (int rr_ = 0; rr_ < 4; ++rr_) {                                       \
      CPASYNC16(du_ + rr_ * 4096, Ug + (kb_ + rA + rr_ * 8) * 128 + cA);      \
      CPASYNC16(dv_ + rr_ * 4096, Vg + (long)(kb_ + rA + rr_ * 8) * NT + Tb + cA); \
    }                                                                         \
    CPCOMMIT();                                                               \
  } while (0)

  STAGE(0, 0);
  CPWAIT0();
  __syncthreads();

  float acc[64];
#pragma unroll
  for (int i = 0; i < 64; ++i) acc[i] = 0.f;

  for (int ch = 0; ch < 8; ++ch) {
    const int cur = ch & 1, nxt = cur ^ 1;
    STAGE(nxt, ch + 1);   // chunk 8 = rows 256..287 < KP=288 (zero pads)
    const float* bU = sU + cur * 4096;
    const float* bV = sV + cur * 4096;
#pragma unroll
    for (int k = 0; k < 32; ++k) {
      const float4 ua = *(const float4*)&bU[k * 128 + og * 8];
      const float4 ub = *(const float4*)&bU[k * 128 + og * 8 + 4];
      const float4 va = *(const float4*)&bV[k * 128 + tg * 8];
      const float4 vb = *(const float4*)&bV[k * 128 + tg * 8 + 4];
      const float uu[8] = {ua.x, ua.y, ua.z, ua.w, ub.x, ub.y, ub.z, ub.w};
      const float vv[8] = {va.x, va.y, va.z, va.w, vb.x, vb.y, vb.z, vb.w};
#pragma unroll
      for (int j = 0; j < 8; ++j)
#pragma unroll
        for (int i = 0; i < 8; ++i) acc[j * 8 + i] += uu[j] * vv[i];
    }
    CPWAIT0();
    __syncthreads();
  }
  // peeled final step: k = 256 = row 0 of chunk 8, which sits in buffer 0
  {
    const float4 ua = *(const float4*)&sU[og * 8];
    const float4 ub = *(const float4*)&sU[og * 8 + 4];
    const float4 va = *(const float4*)&sV[tg * 8];
    const float4 vb = *(const float4*)&sV[tg * 8 + 4];
    const float uu[8] = {ua.x, ua.y, ua.z, ua.w, ub.x, ub.y, ub.z, ub.w};
    const float vv[8] = {va.x, va.y, va.z, va.w, vb.x, vb.y, vb.z, vb.w};
#pragma unroll
    for (int j = 0; j < 8; ++j)
#pragma unroll
      for (int i = 0; i < 8; ++i) acc[j * 8 + i] += uu[j] * vv[i];
  }
#undef STAGE

#pragma unroll
  for (int j = 0; j < 8; ++j) {
    float* dst = g_M + ((long)p * 128 + og * 8 + j) * NT + Tb + tg * 8;
    ((float4*)dst)[0] = make_float4(acc[j*8+0], acc[j*8+1], acc[j*8+2], acc[j*8+3]);
    ((float4*)dst)[1] = make_float4(acc[j*8+4], acc[j*8+5], acc[j*8+6], acc[j*8+7]);
  }
}

// ---------------------------------------------------------------------------
// Kernel D: output transform  Y = A^T M A  (+bias) -> g_z  + FUSED BN1 stats.
// ---------------------------------------------------------------------------
__global__ __launch_bounds__(256) void oT_kernel(const float* __restrict__ b1) {
  const int t = threadIdx.x;
  const int lane = t & 31;
  const int i = blockIdx.x * 256 + t;
  const int tile = i % TPB;
  const int boc = i / TPB;
  const int oc = boc & 127, b = boc >> 7;
  const int Ti = b * TPB + tile;

  float m[6][6];
#pragma unroll
  for (int p = 0; p < 36; ++p)
    m[p / 6][p % 6] = g_M[((long)p * 128 + oc) * NT + Ti];

  float s[4][6];
#pragma unroll
  for (int c = 0; c < 6; ++c) {
    s[0][c] = m[0][c] + m[1][c] + m[2][c] + m[3][c] + m[4][c];
    s[1][c] = m[1][c] - m[2][c] + 2.f * m[3][c] - 2.f * m[4][c];
    s[2][c] = m[1][c] + m[2][c] + 4.f * m[3][c] + 4.f * m[4][c];
    s[3][c] = m[1][c] - m[2][c] + 8.f * m[3][c] - 8.f * m[4][c] + m[5][c];
  }
  const float bb = b1[oc];
  const int ty = tile / 14, tx = tile - ty * 14;
  float* dst = g_z + ((b * 128 + oc) * HH + 4 * ty) * HH + 4 * tx;
  float fs = 0.f, fq = 0.f;
#pragma unroll
  for (int r = 0; r < 4; ++r) {
    float y0 = s[r][0] + s[r][1] + s[r][2] + s[r][3] + s[r][4] + bb;
    float y1 = s[r][1] - s[r][2] + 2.f * s[r][3] - 2.f * s[r][4] + bb;
    float y2 = s[r][1] + s[r][2] + 4.f * s[r][3] + 4.f * s[r][4] + bb;
    float y3 = s[r][1] - s[r][2] + 8.f * s[r][3] - 8.f * s[r][4] + s[r][5] + bb;
    *(float4*)(dst + r * HH) = make_float4(y0, y1, y2, y3);
    fs += y0 + y1 + y2 + y3;
    fq += y0 * y0 + y1 * y1 + y2 * y2 + y3 * y3;
  }
  const unsigned grp = __match_any_sync(0xffffffffu, boc);
#pragma unroll
  for (int off = 16; off; off >>= 1) {
    float as = __shfl_down_sync(0xffffffffu, fs, off);
    float aq = __shfl_down_sync(0xffffffffu, fq, off);
    const int src = lane + off;
    if (src < 32 && ((grp >> src) & 1u)) { fs += as; fq += aq; }
  }
  if (lane == (int)(__ffs(grp) - 1)) {
    atomicAdd(&g_sd1[oc], (double)fs);
    atomicAdd(&g_qd1[oc], (double)fq);
  }
}

// tiny: finalize BN1 mean/rsqrt from atomic accumulators
__global__ __launch_bounds__(128) void reduce1_kernel() {
  const int c = threadIdx.x;
  double m   = g_sd1[c] / N1;
  double var = g_qd1[c] / N1 - m * m;
  g_m1[c]  = (float)m;
  g_rs1[c] = rsqrtf((float)var + 1e-5f);
}

// ---------------------------------------------------------------------------
// Threefry2x32, key (0,42), partitionable draw: x0=0, x1=j, out = o0^o1.
// ---------------------------------------------------------------------------
__device__ __forceinline__ unsigned tf_xor(unsigned j) {
  const unsigned ks0 = 0u, ks1 = 42u, ks2 = 0x1BD11BDAu ^ 42u;
  unsigned x0 = 0u + ks0;
  unsigned x1 = j  + ks1;
#define TFRND(r) { x0 += x1; x1 = __funnelshift_l(x1, x1, r); x1 ^= x0; }
  TFRND(13) TFRND(15) TFRND(26) TFRND(6)
  x0 += ks1; x1 += ks2 + 1u;
  TFRND(17) TFRND(29) TFRND(16) TFRND(24)
  x0 += ks2; x1 += ks0 + 2u;
  TFRND(13) TFRND(15) TFRND(26) TFRND(6)
  x0 += ks0; x1 += ks1 + 3u;
  TFRND(17) TFRND(29) TFRND(16) TFRND(24)
  x0 += ks1; x1 += ks2 + 4u;
  TFRND(13) TFRND(15) TFRND(26) TFRND(6)
  x0 += ks2; x1 += ks0 + 5u;
#undef TFRND
  return x0 ^ x1;
}

// ---------------------------------------------------------------------------
// Kernel 3: BN1 apply + sigmoid + quantize + BEC (in place on g_z)
// ---------------------------------------------------------------------------
__global__ __launch_bounds__(256) void bec_kernel(
    const float* __restrict__ nu, const float* __restrict__ g1,
    const float* __restrict__ be1) {
  const int e = blockIdx.x * 256 + threadIdx.x;
  const int c = (e / PIX) & 127;
  const float z = g_z[e];
  float tt = (z - g_m1[c]) * g_rs1[c] * g1[c] + be1[c];
  float s  = 0.5f * tanhf(0.5f * tt) + 0.5f;
  float r  = rintf(s * 256.0f);
  if (r >= 256.0f) r -= 256.0f;
  const unsigned xb = (unsigned)r;

  const float q = 1.0f - nu[0] * 0.5f;
  unsigned mask = 0u;
#pragma unroll
  for (int k = 0; k < 8; ++k) {
    unsigned bits = tf_xor((unsigned)(k * EZ + e));
    float u = __uint_as_float((bits >> 9) | 0x3f800000u) - 1.0f;
    if (u < q) mask |= (1u << k);
  }
  float outv = ((float)(xb & mask) + (255.0f - (float)mask) / 2.0f) / 255.0f;
  g_z[e] = outv;
}

// ---------------------------------------------------------------------------
// Kernel 4: ConvTranspose2d(k2,s2) 4-tap GEMM + FUSED BN2 partial stats.
// ---------------------------------------------------------------------------
__global__ __launch_bounds__(256) void dec_kernel(
    const float* __restrict__ w4, const float* __restrict__ b4,
    float* __restrict__ out) {
  __shared__ float4 ws4[16 * 64];
  __shared__ float4 hs4[16 * 16];
  const int t = threadIdx.x;
  const int bp = blockIdx.x;
  const int b = bp / 49;
  const int pixb = (bp % 49) * 64;
  const int cb = blockIdx.y * 64;
  const int pgrp = t & 7;
  const int cgrp = t >> 3;

  float acc[64];
#pragma unroll
  for (int i = 0; i < 64; ++i) acc[i] = 0.f;

  const float4* w44 = (const float4*)w4;
  const float4* gz4 = (const float4*)g_z;

  for (int hc0 = 0; hc0 < 128; hc0 += 16) {
    __syncthreads();
#pragma unroll
    for (int i = 0; i < 4; ++i) {
      int idx = t + i * 256;
      int hh = idx >> 6, cl = idx & 63;
      ws4[idx] = w44[(hc0 + hh) * 256 + cb + cl];
    }
    {
      int hh = t >> 4, p4 = t & 15;
      hs4[t] = gz4[((b * 128 + hc0 + hh) * PIX + pixb) / 4 + p4];
    }
    __syncthreads();
#pragma unroll
    for (int hh = 0; hh < 16; ++hh) {
      const float4 h0 = hs4[hh * 16 + pgrp * 2];
      const float4 h1 = hs4[hh * 16 + pgrp * 2 + 1];
      const float4 wa = ws4[hh * 64 + cgrp * 2];
      const float4 wb = ws4[hh * 64 + cgrp * 2 + 1];
      const float hv[8] = {h0.x, h0.y, h0.z, h0.w, h1.x, h1.y, h1.z, h1.w};
#pragma unroll
      for (int pp = 0; pp < 8; ++pp) {
        acc[pp * 4 + 0] += hv[pp] * wa.x;
        acc[pp * 4 + 1] += hv[pp] * wa.y;
        acc[pp * 4 + 2] += hv[pp] * wa.z;
        acc[pp * 4 + 3] += hv[pp] * wa.w;
        acc[32 + pp * 4 + 0] += hv[pp] * wb.x;
        acc[32 + pp * 4 + 1] += hv[pp] * wb.y;
        acc[32 + pp * 4 + 2] += hv[pp] * wb.z;
        acc[32 + pp * 4 + 3] += hv[pp] * wb.w;
      }
    }
  }

  float sums[2] = {0.f, 0.f}, sumq[2] = {0.f, 0.f};
#pragma unroll
  for (int cc = 0; cc < 2; ++cc) {
    const int c = cb + cgrp * 2 + cc;
    const float bb = b4[c];
#pragma unroll
    for (int pp = 0; pp < 8; ++pp) {
      const int pix = pixb + pgrp * 8 + pp;
      const int ih = pix / HH, iw = pix % HH;
      float* dst = out + ((b * 256 + c) * OHH + 2 * ih) * OHH + 2 * iw;
      float v0 = acc[cc * 32 + pp * 4 + 0] + bb;
      float v1 = acc[cc * 32 + pp * 4 + 1] + bb;
      float v2 = acc[cc * 32 + pp * 4 + 2] + bb;
      float v3 = acc[cc * 32 + pp * 4 + 3] + bb;
      *(float2*)dst = make_float2(v0, v1);
      *(float2*)(dst + OHH) = make_float2(v2, v3);
      sums[cc] += v0 + v1 + v2 + v3;
      sumq[cc] += v0 * v0 + v1 * v1 + v2 * v2 + v3 * v3;
    }
  }
#pragma unroll
  for (int off = 1; off < 8; off <<= 1) {
    sums[0] += __shfl_xor_sync(0xffffffffu, sums[0], off);
    sumq[0] += __shfl_xor_sync(0xffffffffu, sumq[0], off);
    sums[1] += __shfl_xor_sync(0xffffffffu, sums[1], off);
    sumq[1] += __shfl_xor_sync(0xffffffffu, sumq[1], off);
  }
  if (pgrp == 0) {
    const int c0 = cb + cgrp * 2;
    atomicAdd(&g_sd2[c0],     (double)sums[0]);
    atomicAdd(&g_qd2[c0],     (double)sumq[0]);
    atomicAdd(&g_sd2[c0 + 1], (double)sums[1]);
    atomicAdd(&g_qd2[c0 + 1], (double)sumq[1]);
  }
}

// ---------------------------------------------------------------------------
// Kernel 6: BN2 apply (stats inline from accumulators) + relu, in place
// ---------------------------------------------------------------------------
__global__ __launch_bounds__(256) void bn2_kernel(
    const float* __restrict__ g2, const float* __restrict__ be2,
    float* __restrict__ out) {
  const int i = blockIdx.x * 256 + threadIdx.x;
  const int c = (i / (OPIX / 4)) & 255;
  const double inv = 1.0 / (double)N2;
  const double md = g_sd2[c] * inv;
  const double var = g_qd2[c] * inv - md * md;
  const float m = (float)md;
  const float rs = rsqrtf((float)var + 1e-5f);
  float4 v = ((float4*)out)[i];
  const float gg = g2[c], bb = be2[c];
  v.x = fmaxf((v.x - m) * rs * gg + bb, 0.f);
  v.y = fmaxf((v.y - m) * rs * gg + bb, 0.f);
  v.z = fmaxf((v.z - m) * rs * gg + bb, 0.f);
  v.w = fmaxf((v.w - m) * rs * gg + bb, 0.f);
  ((float4*)out)[i] = v;
}

// ---------------------------------------------------------------------------
extern "C" void kernel_launch(void* const* d_in, const int* in_sizes, int n_in,
                              void* d_out, int out_size) {
  const float* x   = (const float*)d_in[0];
  const float* nu  = (const float*)d_in[1];
  const float* w1  = (const float*)d_in[2];
  const float* b1  = (const float*)d_in[3];
  const float* g1  = (const float*)d_in[4];
  const float* be1 = (const float*)d_in[5];
  const float* w4  = (const float*)d_in[6];
  const float* b4  = (const float*)d_in[7];
  const float* g2  = (const float*)d_in[8];
  const float* be2 = (const float*)d_in[9];
  float* out = (float*)d_out;

  cudaFuncSetAttribute(wgemm_kernel, cudaFuncAttributeMaxDynamicSharedMemorySize, 65536);

  zero_kernel<<<1, 256>>>();
  uT_kernel<<<(KUSE * 128 + 255) / 256, 256>>>(w1);
  vT_kernel<<<dim3(KUSE, 32), 256>>>(x, nu);
  wgemm_kernel<<<dim3(NT / 128, 36), 256, 65536>>>();
  oT_kernel<<<(BB * 128 * TPB) / 256, 256>>>(b1);
  reduce1_kernel<<<1, 128>>>();
  bec_kernel<<<EZ / 256, 256>>>(nu, g1, be1);
  dec_kernel<<<dim3(32 * 49, 4), 256>>>(w4, b4, out);
  bn2_kernel<<<out_size / 4 / 256, 256>>>(g2, be2, out);
}